// round 6
// baseline (speedup 1.0000x reference)
#include <cuda_runtime.h>
#include <cstdint>
#include <cstddef>

#define NSEQ 768
#define DIMM 384
#define NH 12

#define SCALAR_SCALE 0.14433756729740643f   // (3*16)^-0.5
#define POINT_SCALE  0.13608276348795434f   // (3*4*4.5)^-0.5
#define PAIR_SCALE   0.5773502691896258f    // 3^-0.5

// ---- scratch (device globals; allocations forbidden) ----
__device__ float g_qs  [NSEQ * 192];        // [i][h*16+d]
__device__ float g_ks_t[192 * NSEQ];        // [h*16+d][j]   transposed
__device__ float g_vs_t[192 * NSEQ];        // [h*16+d][j]
__device__ float g_qp  [NSEQ * 144];        // [i][h*12+p*3+c]
__device__ float g_kp_t[144 * NSEQ];        // [h*12+p*3+c][j]
__device__ float g_vp_t[144 * NSEQ];        // [h*12+p*3+c][j]
__device__ float g_results[(size_t)NSEQ * 1920];
__device__ float g_part[4][(size_t)NSEQ * 384];

__device__ __forceinline__ int swz4(int x) { return x ^ (x >> 2); }   // f4-slot swizzle, x in [0,32)

// ---- generic 64x32 fp32 GEMM tile: C = A[M,K] @ B[K,NC] ; tld!=0 => C[col*tld+row] ----
__device__ __forceinline__ void gemm_tile(
    const float* __restrict__ A, const float* __restrict__ B,
    float* __restrict__ C, int K, int NC, int r0, int c0, int tld)
{
    __shared__ float As[64][33];
    __shared__ float Bs[32][33];
    const int tid = threadIdx.x;
    const int ty = tid >> 4, tx = tid & 15;
    float acc[4][2] = {{0.f,0.f},{0.f,0.f},{0.f,0.f},{0.f,0.f}};

    for (int k0 = 0; k0 < K; k0 += 32) {
        #pragma unroll
        for (int l = 0; l < 2; l++) {
            int fidx = tid + l * 256;
            int row = fidx >> 3, c4 = (fidx & 7) * 4;
            float4 v = *(const float4*)(A + (size_t)(r0 + row) * K + k0 + c4);
            As[row][c4 + 0] = v.x; As[row][c4 + 1] = v.y;
            As[row][c4 + 2] = v.z; As[row][c4 + 3] = v.w;
        }
        #pragma unroll
        for (int l = 0; l < 4; l++) {
            int fidx = tid + l * 256;
            int kk = fidx >> 5, cc = fidx & 31;
            int col = c0 + cc;
            Bs[kk][cc] = (col < NC) ? B[(size_t)(k0 + kk) * NC + col] : 0.f;
        }
        __syncthreads();
        #pragma unroll
        for (int kk = 0; kk < 32; kk++) {
            float b0 = Bs[kk][tx * 2 + 0];
            float b1 = Bs[kk][tx * 2 + 1];
            #pragma unroll
            for (int m = 0; m < 4; m++) {
                float a = As[ty * 4 + m][kk];
                acc[m][0] += a * b0;
                acc[m][1] += a * b1;
            }
        }
        __syncthreads();
    }
    #pragma unroll
    for (int m = 0; m < 4; m++) {
        int row = r0 + ty * 4 + m;
        #pragma unroll
        for (int n = 0; n < 2; n++) {
            int col = c0 + tx * 2 + n;
            if (col < NC) {
                if (tld) C[(size_t)col * tld + row] = acc[m][n];
                else     C[(size_t)row * NC  + col] = acc[m][n];
            }
        }
    }
}

// ---- K1: six projection GEMMs; k/v outputs transposed ----
__global__ __launch_bounds__(256) void proj_kernel(
    const float* __restrict__ x,
    const float* __restrict__ Wqs, const float* __restrict__ Wks, const float* __restrict__ Wvs,
    const float* __restrict__ Wqp, const float* __restrict__ Wkp, const float* __restrict__ Wvp)
{
    const float* W; float* C; int NC; int tld;
    switch (blockIdx.z) {
        case 0: W = Wqs; C = g_qs;   NC = 192; tld = 0;    break;
        case 1: W = Wks; C = g_ks_t; NC = 192; tld = NSEQ; break;
        case 2: W = Wvs; C = g_vs_t; NC = 192; tld = NSEQ; break;
        case 3: W = Wqp; C = g_qp;   NC = 144; tld = 0;    break;
        case 4: W = Wkp; C = g_kp_t; NC = 144; tld = NSEQ; break;
        default: W = Wvp; C = g_vp_t; NC = 144; tld = NSEQ; break;
    }
    int c0 = blockIdx.y * 32;
    if (c0 >= NC) return;
    gemm_tile(x, W, C, DIMM, NC, blockIdx.x * 64, c0, tld);
}

// ---- K1b: rotate qp (row-major, in place) ----
__global__ __launch_bounds__(256) void rot_q_kernel(
    const float* __restrict__ R, const float* __restrict__ T)
{
    int tid = blockIdx.x * 256 + threadIdx.x;
    if (tid >= NSEQ * 48) return;
    int i = tid / 48, item = tid - i * 48;
    float* base = g_qp + (size_t)i * 144 + item * 3;
    float l0 = base[0], l1 = base[1], l2 = base[2];
    const float* Ri = R + (size_t)i * 9;
    const float* Ti = T + (size_t)i * 3;
    base[0] = Ri[0]*l0 + Ri[1]*l1 + Ri[2]*l2 + Ti[0];
    base[1] = Ri[3]*l0 + Ri[4]*l1 + Ri[5]*l2 + Ti[1];
    base[2] = Ri[6]*l0 + Ri[7]*l1 + Ri[8]*l2 + Ti[2];
}

// ---- K1c: rotate kp_t / vp_t (transposed layout, coalesced over i) ----
__global__ __launch_bounds__(256) void rot_kv_kernel(
    const float* __restrict__ R, const float* __restrict__ T)
{
    int tid = blockIdx.x * 256 + threadIdx.x;   // 2 * 48 * 768
    if (tid >= 2 * 48 * NSEQ) return;
    int t = tid / (48 * NSEQ);
    int rem = tid - t * (48 * NSEQ);
    int item = rem / NSEQ;
    int i = rem - item * NSEQ;
    float* arr = t ? g_vp_t : g_kp_t;
    float* r0p = arr + (size_t)(item * 3 + 0) * NSEQ + i;
    float* r1p = arr + (size_t)(item * 3 + 1) * NSEQ + i;
    float* r2p = arr + (size_t)(item * 3 + 2) * NSEQ + i;
    float l0 = *r0p, l1 = *r1p, l2 = *r2p;
    const float* Ri = R + (size_t)i * 9;
    const float* Ti = T + (size_t)i * 3;
    *r0p = Ri[0]*l0 + Ri[1]*l1 + Ri[2]*l2 + Ti[0];
    *r1p = Ri[3]*l0 + Ri[4]*l1 + Ri[5]*l2 + Ti[1];
    *r2p = Ri[6]*l0 + Ri[7]*l1 + Ri[8]*l2 + Ti[2];
}

// ================= fused logits + online softmax + aggregation =================
// 2 query rows per CTA (i0, i0+384); 24 chunks of 32 keys; pairwise via cp.async
// double buffer; k/v read直接 from L2 in transposed layout.

// smem float offsets
#define OFF_WPT  16896      // pw tiles: 2q x 2buf x (32*33 f4) = 16896 floats
#define OFF_QS   18432
#define OFF_QP   18816
#define OFF_LBA  19104      // 2 x 12 x 33
#define OFF_LBB  19896
#define OFF_WS   20688      // 24 x 33
#define OFF_BP   21480
#define OFF_CF   21492
#define OFF_RMAX 21504
#define OFF_RSUM 21528
#define OFF_SCL  21552
#define OFF_PT   21576      // 2 x 144
#define SMEM_FL  21864
#define SMEM_BYTES (SMEM_FL * 4)

__global__ __launch_bounds__(512, 2) void fused_attn_kernel(
    const float* __restrict__ pairwise, const float* __restrict__ Wp,
    const float* __restrict__ bp, const float* __restrict__ pwts,
    const float* __restrict__ rotations, const float* __restrict__ translations)
{
    extern __shared__ float sm[];
    float4* smf4 = (float4*)sm;
    const int i0 = blockIdx.x;          // rows i0 and i0+384
    const int tid = threadIdx.x;
    const uint32_t sbase = (uint32_t)__cvta_generic_to_shared(sm);

    // ---- prologue ----
    for (int idx = tid; idx < NH * 128; idx += 512) {        // W_pair transposed+swizzled
        int h = idx >> 7, d = idx & 127;
        sm[OFF_WPT + h * 128 + swz4(d >> 2) * 4 + (d & 3)] = Wp[d * NH + h];
    }
    if (tid < 384) {
        int q = tid / 192, r = tid - q * 192;
        sm[OFF_QS + tid] = g_qs[(size_t)(i0 + q * 384) * 192 + r];
    }
    if (tid < 288) {
        int q = tid / 144, r = tid - q * 144;
        sm[OFF_QP + tid] = g_qp[(size_t)(i0 + q * 384) * 144 + r];
    }
    if (tid < NH) {
        sm[OFF_BP + tid] = bp[tid];
        sm[OFF_CF + tid] = 0.5f * POINT_SCALE * log1pf(expf(pwts[tid]));
    }
    if (tid < 24) { sm[OFF_RMAX + tid] = -1e30f; sm[OFF_RSUM + tid] = 0.f; }

    // persistent accumulators
    float4 pacc0 = {0,0,0,0}, pacc1 = {0,0,0,0};     // r_pair (warps 0-11)
    float sc3[3] = {0,0,0};                           // r_scalar (warps 12-15)
    float pt3[3] = {0,0,0};                           // r_point  (warps 12-15)

    // stage helper: chunk jc -> buffer b (2048 f4 via cp.async)
    auto stage = [&](int jc, int b) {
        #pragma unroll
        for (int l = 0; l < 4; l++) {
            int gi = tid + l * 512;
            int q = gi >> 10, idx = gi & 1023;
            int slot = (q * 2 + b) * 1056 + (idx >> 5) * 33 + swz4(idx & 31);
            const float4* src = (const float4*)pairwise +
                ((size_t)(i0 + q * 384) * NSEQ + jc) * 32 + idx;
            uint32_t daddr = sbase + (uint32_t)slot * 16;
            asm volatile("cp.async.cg.shared.global [%0], [%1], 16;\n"
                         :: "r"(daddr), "l"(src) : "memory");
        }
        asm volatile("cp.async.commit_group;\n" ::: "memory");
    };

    stage(0, 0);
    int buf = 0;

    for (int ic = 0; ic < 24; ic++) {
        const int jc = ic * 32;
        if (ic + 1 < 24) {
            stage(jc + 32, buf ^ 1);
            asm volatile("cp.async.wait_group 1;\n" ::: "memory");
        } else {
            asm volatile("cp.async.wait_group 0;\n" ::: "memory");
        }
        __syncthreads();

        // ---- B1: pair bias, register-blocked over all 12 heads (all 512 threads) ----
        {
            int q = tid >> 8, t8 = tid & 255;
            int j = t8 >> 3, dg = t8 & 7;
            const float4* pw4 = smf4 + (q * 2 + buf) * 1056 + j * 33;
            float4 p[4];
            #pragma unroll
            for (int t = 0; t < 4; t++) p[t] = pw4[swz4(dg * 4 + t)];
            float partial[12];
            #pragma unroll
            for (int h = 0; h < 12; h++) {
                const float4* w4 = smf4 + (OFF_WPT >> 2) + h * 32;
                float s = 0.f;
                #pragma unroll
                for (int t = 0; t < 4; t++) {
                    float4 wv = w4[swz4(dg * 4 + t)];
                    s += p[t].x*wv.x; s += p[t].y*wv.y; s += p[t].z*wv.z; s += p[t].w*wv.w;
                }
                partial[h] = s;
            }
            #pragma unroll
            for (int h = 0; h < 12; h++) {
                float v = partial[h];
                v += __shfl_down_sync(0xffffffffu, v, 4, 8);
                v += __shfl_down_sync(0xffffffffu, v, 2, 8);
                v += __shfl_down_sync(0xffffffffu, v, 1, 8);
                if (dg == 0)
                    sm[OFF_LBA + q * 396 + h * 33 + j] = PAIR_SCALE * (v + sm[OFF_BP + h]);
            }
        }

        // ---- B2: scalar dot + point distance (warps 0-11), direct coalesced L2 reads ----
        if (tid < 384) {
            int q = tid / 192, r = tid - q * 192;
            int hg = r >> 5, j = r & 31;
            #pragma unroll
            for (int e = 0; e < 2; e++) {
                int h = 2 * hg + e;
                float dot = 0.f;
                #pragma unroll
                for (int d = 0; d < 16; d++) {
                    float kv = g_ks_t[(size_t)(h * 16 + d) * NSEQ + jc + j];
                    dot += kv * sm[OFF_QS + q * 192 + h * 16 + d];
                }
                float pd = 0.f;
                #pragma unroll
                for (int c = 0; c < 12; c++) {
                    float kv = g_kp_t[(size_t)(h * 12 + c) * NSEQ + jc + j];
                    float dd = sm[OFF_QP + q * 144 + h * 12 + c] - kv;
                    pd += dd * dd;
                }
                sm[OFF_LBB + q * 396 + h * 33 + j] =
                    SCALAR_SCALE * dot - sm[OFF_CF + h] * pd;
            }
        }
        __syncthreads();

        // ---- C: online softmax update; warp handles (q,h) pairs ----
        {
            int wid = tid >> 5, lane = tid & 31;
            for (int pr = wid; pr < 24; pr += 16) {
                int q = pr / 12, h = pr - q * 12;
                float v = sm[OFF_LBA + q * 396 + h * 33 + lane] +
                          sm[OFF_LBB + q * 396 + h * 33 + lane];
                float cmax = v;
                #pragma unroll
                for (int o = 16; o; o >>= 1)
                    cmax = fmaxf(cmax, __shfl_xor_sync(0xffffffffu, cmax, o));
                float old = sm[OFF_RMAX + pr];
                float nm = fmaxf(old, cmax);
                float e = __expf(v - nm);
                sm[OFF_WS + pr * 33 + lane] = e;
                float cs = e;
                #pragma unroll
                for (int o = 16; o; o >>= 1) cs += __shfl_xor_sync(0xffffffffu, cs, o);
                if (lane == 0) {
                    float scl = __expf(old - nm);
                    sm[OFF_SCL + pr] = scl;
                    sm[OFF_RSUM + pr] = sm[OFF_RSUM + pr] * scl + cs;
                    sm[OFF_RMAX + pr] = nm;
                }
            }
        }
        __syncthreads();

        // ---- D: rescale + accumulate ----
        if (tid < 384) {                      // r_pair: (q, hg, d4), 2 heads each
            int q = tid / 192, r = tid - q * 192;
            int hg = r >> 5, d4 = r & 31;
            int h0 = 2 * hg, h1 = h0 + 1;
            float s0 = sm[OFF_SCL + q * 12 + h0], s1 = sm[OFF_SCL + q * 12 + h1];
            pacc0.x *= s0; pacc0.y *= s0; pacc0.z *= s0; pacc0.w *= s0;
            pacc1.x *= s1; pacc1.y *= s1; pacc1.z *= s1; pacc1.w *= s1;
            const float4* pwt = smf4 + (q * 2 + buf) * 1056;
            const float* w0 = sm + OFF_WS + (q * 12 + h0) * 33;
            const float* w1 = sm + OFF_WS + (q * 12 + h1) * 33;
            int slot = swz4(d4);
            #pragma unroll
            for (int jj = 0; jj < 32; jj++) {
                float4 p = pwt[jj * 33 + slot];
                float a = w0[jj], b = w1[jj];
                pacc0.x += a*p.x; pacc0.y += a*p.y; pacc0.z += a*p.z; pacc0.w += a*p.w;
                pacc1.x += b*p.x; pacc1.y += b*p.y; pacc1.z += b*p.z; pacc1.w += b*p.w;
            }
        } else {                              // warps 12-15: r_scalar then r_point
            int t2 = tid - 384;
            #pragma unroll
            for (int k = 0; k < 3; k++) {     // r_scalar: 384 items
                int it = t2 + k * 128;
                int q = it / 192, rem = it - q * 192;
                int vh = rem >> 4;
                sc3[k] *= sm[OFF_SCL + q * 12 + vh];
                const float4* src = (const float4*)(g_vs_t + (size_t)rem * NSEQ + jc);
                const float* wr = sm + OFF_WS + (q * 12 + vh) * 33;
                #pragma unroll
                for (int j4 = 0; j4 < 8; j4++) {
                    float4 v = src[j4];
                    sc3[k] += wr[j4*4+0]*v.x; sc3[k] += wr[j4*4+1]*v.y;
                    sc3[k] += wr[j4*4+2]*v.z; sc3[k] += wr[j4*4+3]*v.w;
                }
            }
            #pragma unroll
            for (int k = 0; k < 3; k++) {     // r_point: 288 coords
                int ct = t2 + k * 128;
                if (ct < 288) {
                    int q = ct / 144, rem = ct - q * 144;
                    int h = rem / 12;
                    pt3[k] *= sm[OFF_SCL + q * 12 + h];
                    const float4* src = (const float4*)(g_vp_t + (size_t)rem * NSEQ + jc);
                    const float* wr = sm + OFF_WS + (q * 12 + h) * 33;
                    #pragma unroll
                    for (int j4 = 0; j4 < 8; j4++) {
                        float4 v = src[j4];
                        pt3[k] += wr[j4*4+0]*v.x; pt3[k] += wr[j4*4+1]*v.y;
                        pt3[k] += wr[j4*4+2]*v.z; pt3[k] += wr[j4*4+3]*v.w;
                    }
                }
            }
        }
        __syncthreads();
        buf ^= 1;
    }

    // ---- epilogue ----
    if (tid < 384) {                          // r_pair normalize + write
        int q = tid / 192, r = tid - q * 192;
        int hg = r >> 5, d4 = r & 31;
        int h0 = 2 * hg, h1 = h0 + 1;
        float* res = g_results + (size_t)(i0 + q * 384) * 1920;
        float i0v = 1.f / sm[OFF_RSUM + q * 12 + h0];
        float i1v = 1.f / sm[OFF_RSUM + q * 12 + h1];
        float4 o0 = { pacc0.x*i0v, pacc0.y*i0v, pacc0.z*i0v, pacc0.w*i0v };
        float4 o1 = { pacc1.x*i1v, pacc1.y*i1v, pacc1.z*i1v, pacc1.w*i1v };
        *(float4*)(res + 384 + h0 * 128 + d4 * 4) = o0;
        *(float4*)(res + 384 + h1 * 128 + d4 * 4) = o1;
    } else {
        int t2 = tid - 384;
        #pragma unroll
        for (int k = 0; k < 3; k++) {         // r_scalar write
            int it = t2 + k * 128;
            int q = it / 192, rem = it - q * 192;
            int vh = rem >> 4;
            g_results[(size_t)(i0 + q * 384) * 1920 + rem] =
                sc3[k] / sm[OFF_RSUM + q * 12 + vh];
        }
        #pragma unroll
        for (int k = 0; k < 3; k++) {         // r_point to pt_buf (global frame, normalized)
            int ct = t2 + k * 128;
            if (ct < 288) {
                int q = ct / 144, rem = ct - q * 144;
                int h = rem / 12;
                sm[OFF_PT + q * 144 + rem] = pt3[k] / sm[OFF_RSUM + q * 12 + h];
            }
        }
    }
    __syncthreads();
    if (tid < 96) {                           // subtract T, inverse rotate, norms
        int q = tid / 48, r = tid - q * 48;
        int h = r >> 2, p = r & 3;
        int iq = i0 + q * 384;
        float* res = g_results + (size_t)iq * 1920;
        const float* R = rotations + (size_t)iq * 9;
        const float* T = translations + (size_t)iq * 3;
        const float* pb = sm + OFF_PT + q * 144 + h * 12 + p * 3;
        float gx = pb[0] - T[0], gy = pb[1] - T[1], gz = pb[2] - T[2];
        float l0 = gx * R[0] + gy * R[3] + gz * R[6];
        float l1 = gx * R[1] + gy * R[4] + gz * R[7];
        float l2 = gx * R[2] + gy * R[5] + gz * R[8];
        res[192 + h * 12 + p * 3 + 0] = l0;
        res[192 + h * 12 + p * 3 + 1] = l1;
        res[192 + h * 12 + p * 3 + 2] = l2;
        res[336 + h * 4 + p] = sqrtf(l0*l0 + l1*l1 + l2*l2 + 1e-8f);
    }
}

// ---- K4a: out GEMM split-K (768x1920)@(1920x384) -> 4 partials ----
__global__ __launch_bounds__(256) void out_part_kernel(const float* __restrict__ Wout)
{
    __shared__ float As[64][33];
    __shared__ float Bs[32][33];
    const int tid = threadIdx.x;
    const int ty = tid >> 4, tx = tid & 15;
    const int r0 = blockIdx.x * 64, c0 = blockIdx.y * 32;
    const int ks = blockIdx.z * 480;
    float acc[4][2] = {{0.f,0.f},{0.f,0.f},{0.f,0.f},{0.f,0.f}};

    for (int k0 = 0; k0 < 480; k0 += 32) {
        #pragma unroll
        for (int l = 0; l < 2; l++) {
            int fidx = tid + l * 256;
            int row = fidx >> 3, c4 = (fidx & 7) * 4;
            float4 v = *(const float4*)(g_results + (size_t)(r0 + row) * 1920 + ks + k0 + c4);
            As[row][c4+0]=v.x; As[row][c4+1]=v.y; As[row][c4+2]=v.z; As[row][c4+3]=v.w;
        }
        #pragma unroll
        for (int l = 0; l < 4; l++) {
            int fidx = tid + l * 256;
            int kk = fidx >> 5, cc = fidx & 31;
            Bs[kk][cc] = Wout[(size_t)(ks + k0 + kk) * 384 + c0 + cc];
        }
        __syncthreads();
        #pragma unroll
        for (int kk = 0; kk < 32; kk++) {
            float b0 = Bs[kk][tx*2+0], b1 = Bs[kk][tx*2+1];
            #pragma unroll
            for (int m = 0; m < 4; m++) {
                float a = As[ty*4+m][kk];
                acc[m][0] += a * b0;
                acc[m][1] += a * b1;
            }
        }
        __syncthreads();
    }
    float* dst = g_part[blockIdx.z];
    #pragma unroll
    for (int m = 0; m < 4; m++) {
        int row = r0 + ty*4 + m;
        #pragma unroll
        for (int n = 0; n < 2; n++)
            dst[(size_t)row * 384 + c0 + tx*2 + n] = acc[m][n];
    }
}

// ---- K4b: sum partials + bias ----
__global__ __launch_bounds__(256) void add_out_kernel(
    const float* __restrict__ bout, float* __restrict__ out)
{
    int idx = blockIdx.x * 256 + threadIdx.x;
    if (idx >= NSEQ * 384) return;
    out[idx] = g_part[0][idx] + g_part[1][idx] + g_part[2][idx] + g_part[3][idx]
             + bout[idx % 384];
}

extern "C" void kernel_launch(void* const* d_in, const int* in_sizes, int n_in,
                              void* d_out, int out_size) {
    const float* x     = (const float*)d_in[0];
    const float* pairw = (const float*)d_in[1];
    const float* rots  = (const float*)d_in[2];
    const float* trans = (const float*)d_in[3];
    // d_in[4] = mask (all true) — unused
    const float* Wqs   = (const float*)d_in[5];
    const float* Wks   = (const float*)d_in[6];
    const float* Wvs   = (const float*)d_in[7];
    const float* Wqp   = (const float*)d_in[8];
    const float* Wkp   = (const float*)d_in[9];
    const float* Wvp   = (const float*)d_in[10];
    const float* Wpair = (const float*)d_in[11];
    const float* bpair = (const float*)d_in[12];
    const float* pwts  = (const float*)d_in[13];
    const float* Wout  = (const float*)d_in[14];
    const float* bout  = (const float*)d_in[15];
    float* out = (float*)d_out;

    static bool attr_set = false;
    if (!attr_set) {
        cudaFuncSetAttribute(fused_attn_kernel,
                             cudaFuncAttributeMaxDynamicSharedMemorySize, SMEM_BYTES);
        attr_set = true;
    }

    proj_kernel<<<dim3(NSEQ / 64, 6, 6), 256>>>(x, Wqs, Wks, Wvs, Wqp, Wkp, Wvp);
    rot_q_kernel<<<(NSEQ * 48 + 255) / 256, 256>>>(rots, trans);
    rot_kv_kernel<<<(2 * 48 * NSEQ + 255) / 256, 256>>>(rots, trans);
    fused_attn_kernel<<<NSEQ / 2, 512, SMEM_BYTES>>>(pairw, Wpair, bpair, pwts, rots, trans);
    out_part_kernel<<<dim3(NSEQ / 64, 384 / 32, 4), 256>>>(Wout);
    add_out_kernel<<<(NSEQ * 384 + 255) / 256, 256>>>(bout, out);
}

// round 7
// speedup vs baseline: 1.2689x; 1.2689x over previous
#include <cuda_runtime.h>
#include <cstdint>
#include <cstddef>

#define NSEQ 768
#define DIMM 384
#define NH 12

#define SCALAR_SCALE 0.14433756729740643f   // (3*16)^-0.5
#define POINT_SCALE  0.13608276348795434f   // (3*4*4.5)^-0.5
#define PAIR_SCALE   0.5773502691896258f    // 3^-0.5

// ---- scratch (device globals; allocations forbidden) ----
__device__ float g_qs  [NSEQ * 192];        // [i][h*16+d]
__device__ float g_ks_t[192 * NSEQ];        // [h*16+d][j]   transposed (for coalesced dot)
__device__ float g_vs  [NSEQ * 192];        // [j][h*16+d]   row-major (for coalesced agg)
__device__ float g_qp  [NSEQ * 144];        // [i][h*12+p*3+c]
__device__ float g_kp_t[144 * NSEQ];        // [h*12+c][j]   transposed
__device__ float g_vp  [NSEQ * 144];        // [j][h*12+c]   row-major
__device__ float g_results[(size_t)NSEQ * 1920];
__device__ float g_part[4][(size_t)NSEQ * 384];

// ---- generic 64x32 fp32 GEMM tile: C = A[M,K] @ B[K,NC] ; tld!=0 => C[col*tld+row] ----
__device__ __forceinline__ void gemm_tile(
    const float* __restrict__ A, const float* __restrict__ B,
    float* __restrict__ C, int K, int NC, int r0, int c0, int tld)
{
    __shared__ float As[64][33];
    __shared__ float Bs[32][33];
    const int tid = threadIdx.x;
    const int ty = tid >> 4, tx = tid & 15;
    float acc[4][2] = {{0.f,0.f},{0.f,0.f},{0.f,0.f},{0.f,0.f}};

    for (int k0 = 0; k0 < K; k0 += 32) {
        #pragma unroll
        for (int l = 0; l < 2; l++) {
            int fidx = tid + l * 256;
            int row = fidx >> 3, c4 = (fidx & 7) * 4;
            float4 v = *(const float4*)(A + (size_t)(r0 + row) * K + k0 + c4);
            As[row][c4 + 0] = v.x; As[row][c4 + 1] = v.y;
            As[row][c4 + 2] = v.z; As[row][c4 + 3] = v.w;
        }
        #pragma unroll
        for (int l = 0; l < 4; l++) {
            int fidx = tid + l * 256;
            int kk = fidx >> 5, cc = fidx & 31;
            int col = c0 + cc;
            Bs[kk][cc] = (col < NC) ? B[(size_t)(k0 + kk) * NC + col] : 0.f;
        }
        __syncthreads();
        #pragma unroll
        for (int kk = 0; kk < 32; kk++) {
            float b0 = Bs[kk][tx * 2 + 0];
            float b1 = Bs[kk][tx * 2 + 1];
            #pragma unroll
            for (int m = 0; m < 4; m++) {
                float a = As[ty * 4 + m][kk];
                acc[m][0] += a * b0;
                acc[m][1] += a * b1;
            }
        }
        __syncthreads();
    }
    #pragma unroll
    for (int m = 0; m < 4; m++) {
        int row = r0 + ty * 4 + m;
        #pragma unroll
        for (int n = 0; n < 2; n++) {
            int col = c0 + tx * 2 + n;
            if (col < NC) {
                if (tld) C[(size_t)col * tld + row] = acc[m][n];
                else     C[(size_t)row * NC  + col] = acc[m][n];
            }
        }
    }
}

// ---- K1: six projection GEMMs; k transposed, v row-major ----
__global__ __launch_bounds__(256) void proj_kernel(
    const float* __restrict__ x,
    const float* __restrict__ Wqs, const float* __restrict__ Wks, const float* __restrict__ Wvs,
    const float* __restrict__ Wqp, const float* __restrict__ Wkp, const float* __restrict__ Wvp)
{
    const float* W; float* C; int NC; int tld;
    switch (blockIdx.z) {
        case 0: W = Wqs; C = g_qs;   NC = 192; tld = 0;    break;
        case 1: W = Wks; C = g_ks_t; NC = 192; tld = NSEQ; break;
        case 2: W = Wvs; C = g_vs;   NC = 192; tld = 0;    break;
        case 3: W = Wqp; C = g_qp;   NC = 144; tld = 0;    break;
        case 4: W = Wkp; C = g_kp_t; NC = 144; tld = NSEQ; break;
        default: W = Wvp; C = g_vp;  NC = 144; tld = 0;    break;
    }
    int c0 = blockIdx.y * 32;
    if (c0 >= NC) return;
    gemm_tile(x, W, C, DIMM, NC, blockIdx.x * 64, c0, tld);
}

// ---- K1b: rotate qp & vp (row-major, in place) ----
__global__ __launch_bounds__(256) void rot_row_kernel(
    const float* __restrict__ R, const float* __restrict__ T)
{
    int tid = blockIdx.x * 256 + threadIdx.x;
    if (tid >= 2 * NSEQ * 48) return;
    int t = tid / (NSEQ * 48);
    int rem = tid - t * (NSEQ * 48);
    int i = rem / 48, item = rem - i * 48;
    float* base = (t ? g_vp : g_qp) + (size_t)i * 144 + item * 3;
    float l0 = base[0], l1 = base[1], l2 = base[2];
    const float* Ri = R + (size_t)i * 9;
    const float* Ti = T + (size_t)i * 3;
    base[0] = Ri[0]*l0 + Ri[1]*l1 + Ri[2]*l2 + Ti[0];
    base[1] = Ri[3]*l0 + Ri[4]*l1 + Ri[5]*l2 + Ti[1];
    base[2] = Ri[6]*l0 + Ri[7]*l1 + Ri[8]*l2 + Ti[2];
}

// ---- K1c: rotate kp_t (transposed layout, coalesced over j) ----
__global__ __launch_bounds__(256) void rot_kt_kernel(
    const float* __restrict__ R, const float* __restrict__ T)
{
    int tid = blockIdx.x * 256 + threadIdx.x;   // 48*768
    if (tid >= 48 * NSEQ) return;
    int item = tid / NSEQ;
    int i = tid - item * NSEQ;
    float* r0p = g_kp_t + (size_t)(item * 3 + 0) * NSEQ + i;
    float* r1p = g_kp_t + (size_t)(item * 3 + 1) * NSEQ + i;
    float* r2p = g_kp_t + (size_t)(item * 3 + 2) * NSEQ + i;
    float l0 = *r0p, l1 = *r1p, l2 = *r2p;
    const float* Ri = R + (size_t)i * 9;
    const float* Ti = T + (size_t)i * 3;
    *r0p = Ri[0]*l0 + Ri[1]*l1 + Ri[2]*l2 + Ti[0];
    *r1p = Ri[3]*l0 + Ri[4]*l1 + Ri[5]*l2 + Ti[1];
    *r2p = Ri[6]*l0 + Ri[7]*l1 + Ri[8]*l2 + Ti[2];
}

// ================= fused: logits (two-pass) + exact softmax + aggregation ======
// 1 query row per CTA, 768 CTAs. Pairwise streamed twice via cp.async.

#define ASTRIDE 769
#define OFF_ATT  8448               // pw: 2 bufs x 1056 f4 = 8448 floats at 0
#define OFF_W    (OFF_ATT + NH * ASTRIDE)    // 12 x 128
#define OFF_QS   (OFF_W + 1536)
#define OFF_QP   (OFF_QS + 192)
#define OFF_BP   (OFF_QP + 144)
#define OFF_CF   (OFF_BP + 12)
#define OFF_SUM  (OFF_CF + 12)
#define OFF_PT   (OFF_SUM + 12)
#define SMEM_FL  (OFF_PT + 144)
#define SMEM_BYTES (SMEM_FL * 4)

__global__ __launch_bounds__(512, 2) void fused_attn_kernel(
    const float* __restrict__ pairwise, const float* __restrict__ Wp,
    const float* __restrict__ bp, const float* __restrict__ pwts,
    const float* __restrict__ rotations, const float* __restrict__ translations)
{
    extern __shared__ float sm[];
    float4* pw4 = (float4*)sm;
    float* att = sm + OFF_ATT;
    const int i = blockIdx.x;
    const int tid = threadIdx.x;
    const int wid = tid >> 5, lane = tid & 31;
    const uint32_t sbase = (uint32_t)__cvta_generic_to_shared(sm);

    // ---- prologue ----
    for (int idx = tid; idx < NH * 128; idx += 512)           // W_pair transposed [h][d]
        sm[OFF_W + idx] = Wp[(idx & 127) * NH + (idx >> 7)];
    if (tid < 192) sm[OFF_QS + tid] = g_qs[(size_t)i * 192 + tid];
    if (tid < 144) sm[OFF_QP + tid] = g_qp[(size_t)i * 144 + tid];
    if (tid < NH) {
        sm[OFF_BP + tid] = bp[tid];
        sm[OFF_CF + tid] = 0.5f * POINT_SCALE * log1pf(expf(pwts[tid]));
    }

    auto stage = [&](int ic) {
        int b = ic & 1;
        int jc = ic * 32;
        const float4* src = (const float4*)pairwise + ((size_t)i * NSEQ + jc) * 32;
        #pragma unroll
        for (int l = 0; l < 2; l++) {
            int idx = tid + l * 512;
            int slot = b * 1056 + (idx >> 5) * 33 + (idx & 31);
            uint32_t daddr = sbase + (uint32_t)slot * 16;
            asm volatile("cp.async.cg.shared.global [%0], [%1], 16;\n"
                         :: "r"(daddr), "l"(src + idx) : "memory");
        }
        asm volatile("cp.async.commit_group;\n" ::: "memory");
    };
    auto cp_wait1 = [] { asm volatile("cp.async.wait_group 1;\n" ::: "memory"); };
    auto cp_wait0 = [] { asm volatile("cp.async.wait_group 0;\n" ::: "memory"); };

    stage(0); stage(1);

    // ---- B2 prepass: scalar dot + point distance for all j (coalesced, no deps on pw)
    __syncthreads();   // qs/qp/cf ready
    for (int wc = wid; wc < 288; wc += 16) {
        int h = wc / 24, jcc = (wc - h * 24) * 32;
        int j = jcc + lane;
        float dot = 0.f;
        #pragma unroll
        for (int d = 0; d < 16; d++)
            dot += g_ks_t[(size_t)(h * 16 + d) * NSEQ + j] * sm[OFF_QS + h * 16 + d];
        float pd = 0.f;
        #pragma unroll
        for (int c = 0; c < 12; c++) {
            float dd = sm[OFF_QP + h * 12 + c] - g_kp_t[(size_t)(h * 12 + c) * NSEQ + j];
            pd += dd * dd;
        }
        att[h * ASTRIDE + j] = SCALAR_SCALE * dot - sm[OFF_CF + h] * pd;
    }
    __syncthreads();

    // ---- phase 1: pair bias accumulated into att ----
    const int jp = tid >> 5;            // 16 j-pairs; lanes = d-slot (32 f4 of d)
    for (int ic = 0; ic < 24; ic++) {
        if (ic < 23) cp_wait1(); else cp_wait0();
        __syncthreads();
        {
            int b = ic & 1, jc = ic * 32;
            float4 p0 = pw4[b * 1056 + (2 * jp) * 33 + lane];
            float4 p1 = pw4[b * 1056 + (2 * jp + 1) * 33 + lane];
            float r0[12], r1[12];
            #pragma unroll
            for (int h = 0; h < 12; h++) {
                float4 w = ((const float4*)(sm + OFF_W))[h * 32 + lane];
                float a = p0.x*w.x; a += p0.y*w.y; a += p0.z*w.z; a += p0.w*w.w;
                float c = p1.x*w.x; c += p1.y*w.y; c += p1.z*w.z; c += p1.w*w.w;
                r0[h] = a; r1[h] = c;
            }
            #pragma unroll
            for (int h = 0; h < 12; h++) {
                #pragma unroll
                for (int o = 16; o; o >>= 1) {
                    r0[h] += __shfl_xor_sync(0xffffffffu, r0[h], o);
                    r1[h] += __shfl_xor_sync(0xffffffffu, r1[h], o);
                }
            }
            float out0 = r0[0], out1 = r1[0];
            #pragma unroll
            for (int h = 1; h < 12; h++) {
                if (lane == h)      out0 = r0[h];
                if (lane == 16 + h) out1 = r1[h];
            }
            if (lane < 12)
                att[lane * ASTRIDE + jc + 2 * jp] += PAIR_SCALE * (out0 + sm[OFF_BP + lane]);
            else if (lane >= 16 && lane < 28)
                att[(lane - 16) * ASTRIDE + jc + 2 * jp + 1] +=
                    PAIR_SCALE * (out1 + sm[OFF_BP + lane - 16]);
        }
        __syncthreads();
        if (ic + 2 < 24) stage(ic + 2);
    }

    // ---- restage for phase 2, softmax overlaps the cp latency ----
    stage(0); stage(1);
    if (wid < 12) {                     // exact softmax per head; att <- exp(v-m), sum stored
        float* row = att + wid * ASTRIDE;
        float m = -1e30f;
        for (int j = lane; j < NSEQ; j += 32) m = fmaxf(m, row[j]);
        #pragma unroll
        for (int o = 16; o; o >>= 1) m = fmaxf(m, __shfl_xor_sync(0xffffffffu, m, o));
        float s = 0.f;
        for (int j = lane; j < NSEQ; j += 32) {
            float e = __expf(row[j] - m);
            row[j] = e;
            s += e;
        }
        #pragma unroll
        for (int o = 16; o; o >>= 1) s += __shfl_xor_sync(0xffffffffu, s, o);
        if (lane == 0) sm[OFF_SUM + wid] = s;
    }
    __syncthreads();

    // ---- phase 2: aggregation ----
    // warps 0-5: r_pair (2 heads each, lanes = d4). warps 6-15: v_s / v_p items.
    float4 pacc0 = {0,0,0,0}, pacc1 = {0,0,0,0};
    float vacc0 = 0.f, vacc1 = 0.f;
    int it0 = -1, it1 = -1, h0i = 0, h1i = 0, st0 = 0, st1 = 0;
    const float* vb0 = nullptr; const float* vb1 = nullptr;
    if (wid >= 6) {
        int t2 = tid - 192;             // 0..319
        it0 = t2;
        it1 = (t2 < 16) ? t2 + 320 : -1;
        st0 = it0 < 192 ? 192 : 144;
        vb0 = it0 < 192 ? (g_vs + it0) : (g_vp + (it0 - 192));
        h0i = it0 < 192 ? (it0 >> 4) : (it0 - 192) / 12;
        if (it1 >= 0) {
            st1 = 144; vb1 = g_vp + (it1 - 192);
            h1i = (it1 - 192) / 12;
        }
    }

    for (int ic = 0; ic < 24; ic++) {
        if (ic < 23) cp_wait1(); else cp_wait0();
        __syncthreads();
        int b = ic & 1, jc = ic * 32;
        if (wid < 6) {
            const float4* pwt = pw4 + b * 1056;
            const float* w0 = att + (2 * wid) * ASTRIDE + jc;
            const float* w1 = w0 + ASTRIDE;
            #pragma unroll
            for (int jj = 0; jj < 32; jj++) {
                float4 p = pwt[jj * 33 + lane];
                float a = w0[jj], c = w1[jj];
                pacc0.x += a*p.x; pacc0.y += a*p.y; pacc0.z += a*p.z; pacc0.w += a*p.w;
                pacc1.x += c*p.x; pacc1.y += c*p.y; pacc1.z += c*p.z; pacc1.w += c*p.w;
            }
        } else {
            const float* w0 = att + h0i * ASTRIDE + jc;
            const float* v0 = vb0 + (size_t)jc * st0;
            #pragma unroll
            for (int jj = 0; jj < 32; jj++) {
                vacc0 += w0[jj] * v0[0];
                v0 += st0;
            }
            if (it1 >= 0) {
                const float* w1 = att + h1i * ASTRIDE + jc;
                const float* v1 = vb1 + (size_t)jc * st1;
                #pragma unroll
                for (int jj = 0; jj < 32; jj++) {
                    vacc1 += w1[jj] * v1[0];
                    v1 += st1;
                }
            }
        }
        __syncthreads();
        if (ic + 2 < 24) stage(ic + 2);
    }

    // ---- epilogue ----
    float* res = g_results + (size_t)i * 1920;
    if (wid < 6) {
        int h0 = 2 * wid, h1 = h0 + 1;
        float i0v = 1.f / sm[OFF_SUM + h0], i1v = 1.f / sm[OFF_SUM + h1];
        float4 o0 = { pacc0.x*i0v, pacc0.y*i0v, pacc0.z*i0v, pacc0.w*i0v };
        float4 o1 = { pacc1.x*i1v, pacc1.y*i1v, pacc1.z*i1v, pacc1.w*i1v };
        *(float4*)(res + 384 + h0 * 128 + lane * 4) = o0;
        *(float4*)(res + 384 + h1 * 128 + lane * 4) = o1;
    } else {
        float r0v = vacc0 / sm[OFF_SUM + h0i];
        if (it0 < 192) res[it0] = r0v;                 // r_scalar -> [0,192)
        else           sm[OFF_PT + it0 - 192] = r0v;   // global-frame point
        if (it1 >= 0)  sm[OFF_PT + it1 - 192] = vacc1 / sm[OFF_SUM + h1i];
    }
    __syncthreads();
    if (tid < 48) {                    // subtract T, inverse rotate, norms
        int h = tid >> 2, p = tid & 3;
        const float* R = rotations + (size_t)i * 9;
        const float* T = translations + (size_t)i * 3;
        const float* pb = sm + OFF_PT + h * 12 + p * 3;
        float gx = pb[0] - T[0], gy = pb[1] - T[1], gz = pb[2] - T[2];
        float l0 = gx * R[0] + gy * R[3] + gz * R[6];
        float l1 = gx * R[1] + gy * R[4] + gz * R[7];
        float l2 = gx * R[2] + gy * R[5] + gz * R[8];
        res[192 + h * 12 + p * 3 + 0] = l0;
        res[192 + h * 12 + p * 3 + 1] = l1;
        res[192 + h * 12 + p * 3 + 2] = l2;
        res[336 + h * 4 + p] = sqrtf(l0*l0 + l1*l1 + l2*l2 + 1e-8f);
    }
}

// ---- K4a: out GEMM split-K (768x1920)@(1920x384) -> 4 partials ----
__global__ __launch_bounds__(256) void out_part_kernel(const float* __restrict__ Wout)
{
    __shared__ float As[64][33];
    __shared__ float Bs[32][33];
    const int tid = threadIdx.x;
    const int ty = tid >> 4, tx = tid & 15;
    const int r0 = blockIdx.x * 64, c0 = blockIdx.y * 32;
    const int ks = blockIdx.z * 480;
    float acc[4][2] = {{0.f,0.f},{0.f,0.f},{0.f,0.f},{0.f,0.f}};

    for (int k0 = 0; k0 < 480; k0 += 32) {
        #pragma unroll
        for (int l = 0; l < 2; l++) {
            int fidx = tid + l * 256;
            int row = fidx >> 3, c4 = (fidx & 7) * 4;
            float4 v = *(const float4*)(g_results + (size_t)(r0 + row) * 1920 + ks + k0 + c4);
            As[row][c4+0]=v.x; As[row][c4+1]=v.y; As[row][c4+2]=v.z; As[row][c4+3]=v.w;
        }
        #pragma unroll
        for (int l = 0; l < 4; l++) {
            int fidx = tid + l * 256;
            int kk = fidx >> 5, cc = fidx & 31;
            Bs[kk][cc] = Wout[(size_t)(ks + k0 + kk) * 384 + c0 + cc];
        }
        __syncthreads();
        #pragma unroll
        for (int kk = 0; kk < 32; kk++) {
            float b0 = Bs[kk][tx*2+0], b1 = Bs[kk][tx*2+1];
            #pragma unroll
            for (int m = 0; m < 4; m++) {
                float a = As[ty*4+m][kk];
                acc[m][0] += a * b0;
                acc[m][1] += a * b1;
            }
        }
        __syncthreads();
    }
    float* dst = g_part[blockIdx.z];
    #pragma unroll
    for (int m = 0; m < 4; m++) {
        int row = r0 + ty*4 + m;
        #pragma unroll
        for (int n = 0; n < 2; n++)
            dst[(size_t)row * 384 + c0 + tx*2 + n] = acc[m][n];
    }
}

// ---- K4b: sum partials + bias ----
__global__ __launch_bounds__(256) void add_out_kernel(
    const float* __restrict__ bout, float* __restrict__ out)
{
    int idx = blockIdx.x * 256 + threadIdx.x;
    if (idx >= NSEQ * 384) return;
    out[idx] = g_part[0][idx] + g_part[1][idx] + g_part[2][idx] + g_part[3][idx]
             + bout[idx % 384];
}

extern "C" void kernel_launch(void* const* d_in, const int* in_sizes, int n_in,
                              void* d_out, int out_size) {
    const float* x     = (const float*)d_in[0];
    const float* pairw = (const float*)d_in[1];
    const float* rots  = (const float*)d_in[2];
    const float* trans = (const float*)d_in[3];
    // d_in[4] = mask (all true) — unused
    const float* Wqs   = (const float*)d_in[5];
    const float* Wks   = (const float*)d_in[6];
    const float* Wvs   = (const float*)d_in[7];
    const float* Wqp   = (const float*)d_in[8];
    const float* Wkp   = (const float*)d_in[9];
    const float* Wvp   = (const float*)d_in[10];
    const float* Wpair = (const float*)d_in[11];
    const float* bpair = (const float*)d_in[12];
    const float* pwts  = (const float*)d_in[13];
    const float* Wout  = (const float*)d_in[14];
    const float* bout  = (const float*)d_in[15];
    float* out = (float*)d_out;

    static bool attr_set = false;
    if (!attr_set) {
        cudaFuncSetAttribute(fused_attn_kernel,
                             cudaFuncAttributeMaxDynamicSharedMemorySize, SMEM_BYTES);
        attr_set = true;
    }

    proj_kernel<<<dim3(NSEQ / 64, 6, 6), 256>>>(x, Wqs, Wks, Wvs, Wqp, Wkp, Wvp);
    rot_row_kernel<<<(2 * NSEQ * 48 + 255) / 256, 256>>>(rots, trans);
    rot_kt_kernel<<<(48 * NSEQ + 255) / 256, 256>>>(rots, trans);
    fused_attn_kernel<<<NSEQ, 512, SMEM_BYTES>>>(pairw, Wpair, bpair, pwts, rots, trans);
    out_part_kernel<<<dim3(NSEQ / 64, 384 / 32, 4), 256>>>(Wout);
    add_out_kernel<<<(NSEQ * 384 + 255) / 256, 256>>>(bout, out);
}

// round 8
// speedup vs baseline: 1.3348x; 1.0519x over previous
#include <cuda_runtime.h>
#include <cstdint>
#include <cstddef>

#define NSEQ 768
#define DIMM 384
#define NH 12

#define SCALAR_SCALE 0.14433756729740643f   // (3*16)^-0.5
#define POINT_SCALE  0.13608276348795434f   // (3*4*4.5)^-0.5
#define PAIR_SCALE   0.5773502691896258f    // 3^-0.5

// ---- scratch (device globals; allocations forbidden) ----
__device__ float g_qs  [NSEQ * 192];        // [i][h*16+d]
__device__ float g_ks_t[192 * NSEQ];        // [h*16+d][j]   transposed (coalesced dot)
__device__ float g_vs  [NSEQ * 192];        // [j][h*16+d]   row-major (coalesced agg)
__device__ float g_qp  [NSEQ * 144];        // [i][h*12+p*3+c]
__device__ float g_kp_t[144 * NSEQ];        // [h*12+c][j]   transposed
__device__ float g_vp  [NSEQ * 144];        // [j][h*12+c]   row-major
__device__ float g_results[(size_t)NSEQ * 1920];
__device__ float g_part[4][(size_t)NSEQ * 384];

// ---- generic 64x32 fp32 GEMM tile: C = A[M,K] @ B[K,NC] ; tld!=0 => C[col*tld+row] ----
__device__ __forceinline__ void gemm_tile(
    const float* __restrict__ A, const float* __restrict__ B,
    float* __restrict__ C, int K, int NC, int r0, int c0, int tld)
{
    __shared__ float As[64][33];
    __shared__ float Bs[32][33];
    const int tid = threadIdx.x;
    const int ty = tid >> 4, tx = tid & 15;
    float acc[4][2] = {{0.f,0.f},{0.f,0.f},{0.f,0.f},{0.f,0.f}};

    for (int k0 = 0; k0 < K; k0 += 32) {
        #pragma unroll
        for (int l = 0; l < 2; l++) {
            int fidx = tid + l * 256;
            int row = fidx >> 3, c4 = (fidx & 7) * 4;
            float4 v = *(const float4*)(A + (size_t)(r0 + row) * K + k0 + c4);
            As[row][c4 + 0] = v.x; As[row][c4 + 1] = v.y;
            As[row][c4 + 2] = v.z; As[row][c4 + 3] = v.w;
        }
        #pragma unroll
        for (int l = 0; l < 4; l++) {
            int fidx = tid + l * 256;
            int kk = fidx >> 5, cc = fidx & 31;
            int col = c0 + cc;
            Bs[kk][cc] = (col < NC) ? B[(size_t)(k0 + kk) * NC + col] : 0.f;
        }
        __syncthreads();
        #pragma unroll
        for (int kk = 0; kk < 32; kk++) {
            float b0 = Bs[kk][tx * 2 + 0];
            float b1 = Bs[kk][tx * 2 + 1];
            #pragma unroll
            for (int m = 0; m < 4; m++) {
                float a = As[ty * 4 + m][kk];
                acc[m][0] += a * b0;
                acc[m][1] += a * b1;
            }
        }
        __syncthreads();
    }
    #pragma unroll
    for (int m = 0; m < 4; m++) {
        int row = r0 + ty * 4 + m;
        #pragma unroll
        for (int n = 0; n < 2; n++) {
            int col = c0 + tx * 2 + n;
            if (col < NC) {
                if (tld) C[(size_t)col * tld + row] = acc[m][n];
                else     C[(size_t)row * NC  + col] = acc[m][n];
            }
        }
    }
}

// ---- K1: six projection GEMMs; k transposed, v row-major ----
__global__ __launch_bounds__(256) void proj_kernel(
    const float* __restrict__ x,
    const float* __restrict__ Wqs, const float* __restrict__ Wks, const float* __restrict__ Wvs,
    const float* __restrict__ Wqp, const float* __restrict__ Wkp, const float* __restrict__ Wvp)
{
    const float* W; float* C; int NC; int tld;
    switch (blockIdx.z) {
        case 0: W = Wqs; C = g_qs;   NC = 192; tld = 0;    break;
        case 1: W = Wks; C = g_ks_t; NC = 192; tld = NSEQ; break;
        case 2: W = Wvs; C = g_vs;   NC = 192; tld = 0;    break;
        case 3: W = Wqp; C = g_qp;   NC = 144; tld = 0;    break;
        case 4: W = Wkp; C = g_kp_t; NC = 144; tld = NSEQ; break;
        default: W = Wvp; C = g_vp;  NC = 144; tld = 0;    break;
    }
    int c0 = blockIdx.y * 32;
    if (c0 >= NC) return;
    gemm_tile(x, W, C, DIMM, NC, blockIdx.x * 64, c0, tld);
}

// ---- K1b: rotate qp & vp (row-major, in place) ----
__global__ __launch_bounds__(256) void rot_row_kernel(
    const float* __restrict__ R, const float* __restrict__ T)
{
    int tid = blockIdx.x * 256 + threadIdx.x;
    if (tid >= 2 * NSEQ * 48) return;
    int t = tid / (NSEQ * 48);
    int rem = tid - t * (NSEQ * 48);
    int i = rem / 48, item = rem - i * 48;
    float* base = (t ? g_vp : g_qp) + (size_t)i * 144 + item * 3;
    float l0 = base[0], l1 = base[1], l2 = base[2];
    const float* Ri = R + (size_t)i * 9;
    const float* Ti = T + (size_t)i * 3;
    base[0] = Ri[0]*l0 + Ri[1]*l1 + Ri[2]*l2 + Ti[0];
    base[1] = Ri[3]*l0 + Ri[4]*l1 + Ri[5]*l2 + Ti[1];
    base[2] = Ri[6]*l0 + Ri[7]*l1 + Ri[8]*l2 + Ti[2];
}

// ---- K1c: rotate kp_t (transposed layout, coalesced over j) ----
__global__ __launch_bounds__(256) void rot_kt_kernel(
    const float* __restrict__ R, const float* __restrict__ T)
{
    int tid = blockIdx.x * 256 + threadIdx.x;   // 48*768
    if (tid >= 48 * NSEQ) return;
    int item = tid / NSEQ;
    int i = tid - item * NSEQ;
    float* r0p = g_kp_t + (size_t)(item * 3 + 0) * NSEQ + i;
    float* r1p = g_kp_t + (size_t)(item * 3 + 1) * NSEQ + i;
    float* r2p = g_kp_t + (size_t)(item * 3 + 2) * NSEQ + i;
    float l0 = *r0p, l1 = *r1p, l2 = *r2p;
    const float* Ri = R + (size_t)i * 9;
    const float* Ti = T + (size_t)i * 3;
    *r0p = Ri[0]*l0 + Ri[1]*l1 + Ri[2]*l2 + Ti[0];
    *r1p = Ri[3]*l0 + Ri[4]*l1 + Ri[5]*l2 + Ti[1];
    *r2p = Ri[6]*l0 + Ri[7]*l1 + Ri[8]*l2 + Ti[2];
}

// ================= fused: logits (two-pass) + exact softmax + aggregation ======
// 1 query row per CTA. Pairwise streamed twice via 4-deep cp.async pipeline.

#define ASTRIDE 769
#define OFF_ATT  16896                       // pw: 4 bufs x 1056 f4 = 16896 floats at 0
#define OFF_W    (OFF_ATT + NH * ASTRIDE)    // 12 x 128
#define OFF_QS   (OFF_W + 1536)
#define OFF_QP   (OFF_QS + 192)
#define OFF_BP   (OFF_QP + 144)
#define OFF_CF   (OFF_BP + 12)
#define OFF_SUM  (OFF_CF + 12)
#define OFF_PT   (OFF_SUM + 12)
#define SMEM_FL  (OFF_PT + 144)
#define SMEM_BYTES (SMEM_FL * 4)

__device__ __forceinline__ void cp_wait_n(int n) {
    if (n <= 0)      asm volatile("cp.async.wait_group 0;\n" ::: "memory");
    else if (n == 1) asm volatile("cp.async.wait_group 1;\n" ::: "memory");
    else             asm volatile("cp.async.wait_group 2;\n" ::: "memory");
}

__global__ __launch_bounds__(512, 2) void fused_attn_kernel(
    const float* __restrict__ pairwise, const float* __restrict__ Wp,
    const float* __restrict__ bp, const float* __restrict__ pwts,
    const float* __restrict__ rotations, const float* __restrict__ translations)
{
    extern __shared__ float sm[];
    float4* pw4 = (float4*)sm;
    float* att = sm + OFF_ATT;
    const int i = blockIdx.x;
    const int tid = threadIdx.x;
    const int wid = tid >> 5, lane = tid & 31;
    const uint32_t sbase = (uint32_t)__cvta_generic_to_shared(sm);

    // ---- prologue ----
    for (int idx = tid; idx < NH * 128; idx += 512)           // W_pair transposed [h][d]
        sm[OFF_W + idx] = Wp[(idx & 127) * NH + (idx >> 7)];
    if (tid < 192) sm[OFF_QS + tid] = g_qs[(size_t)i * 192 + tid];
    if (tid < 144) sm[OFF_QP + tid] = g_qp[(size_t)i * 144 + tid];
    if (tid < NH) {
        sm[OFF_BP + tid] = bp[tid];
        sm[OFF_CF + tid] = 0.5f * POINT_SCALE * log1pf(expf(pwts[tid]));
    }

    auto stage = [&](int ic) {
        int b = ic & 3;
        const float4* src = (const float4*)pairwise + ((size_t)i * NSEQ + ic * 32) * 32;
        #pragma unroll
        for (int l = 0; l < 2; l++) {
            int idx = tid + l * 512;
            int slot = b * 1056 + (idx >> 5) * 33 + (idx & 31);
            uint32_t daddr = sbase + (uint32_t)slot * 16;
            asm volatile("cp.async.cg.shared.global [%0], [%1], 16;\n"
                         :: "r"(daddr), "l"(src + idx) : "memory");
        }
        asm volatile("cp.async.commit_group;\n" ::: "memory");
    };

    stage(0); stage(1); stage(2);

    // ---- B2 prepass: dot + point dist + pair bias const, coalesced (all 16 warps) ----
    __syncthreads();   // qs/qp/cf ready
    for (int wc = wid; wc < 288; wc += 16) {
        int h = wc / 24, jcc = (wc - h * 24) * 32;
        int j = jcc + lane;
        float dot = 0.f;
        #pragma unroll
        for (int d = 0; d < 16; d++)
            dot += g_ks_t[(size_t)(h * 16 + d) * NSEQ + j] * sm[OFF_QS + h * 16 + d];
        float pd = 0.f;
        #pragma unroll
        for (int c = 0; c < 12; c++) {
            float dd = sm[OFF_QP + h * 12 + c] - g_kp_t[(size_t)(h * 12 + c) * NSEQ + j];
            pd += dd * dd;
        }
        att[h * ASTRIDE + j] = SCALAR_SCALE * dot - sm[OFF_CF + h] * pd
                             + PAIR_SCALE * sm[OFF_BP + h];
    }

    // ---- phase 1: pair bias; warp = head, lane = j; no shuffles ----
    for (int ic = 0; ic < 24; ic++) {
        cp_wait_n(23 - ic);
        __syncthreads();                 // data ic ready; compute(ic-1) done everywhere
        if (ic + 3 < 24) stage(ic + 3);
        if (wid < 12) {
            const float4* prow = pw4 + (ic & 3) * 1056 + lane * 33;
            const float4* wrow = ((const float4*)(sm + OFF_W)) + wid * 32;
            float acc = 0.f;
            #pragma unroll
            for (int d = 0; d < 32; d++) {
                float4 p = prow[d];
                float4 w = wrow[d];          // broadcast
                acc += p.x*w.x; acc += p.y*w.y; acc += p.z*w.z; acc += p.w*w.w;
            }
            att[wid * ASTRIDE + ic * 32 + lane] += PAIR_SCALE * acc;
        }
    }

    // ---- restage for phase 2; softmax overlaps cp latency ----
    stage(0); stage(1); stage(2);
    __syncthreads();                      // phase-1 att writes complete
    if (wid < 12) {                       // exact softmax per head
        float* row = att + wid * ASTRIDE;
        float m = -1e30f;
        for (int j = lane; j < NSEQ; j += 32) m = fmaxf(m, row[j]);
        #pragma unroll
        for (int o = 16; o; o >>= 1) m = fmaxf(m, __shfl_xor_sync(0xffffffffu, m, o));
        float s = 0.f;
        for (int j = lane; j < NSEQ; j += 32) {
            float e = __expf(row[j] - m);
            row[j] = e;
            s += e;
        }
        #pragma unroll
        for (int o = 16; o; o >>= 1) s += __shfl_xor_sync(0xffffffffu, s, o);
        if (lane == 0) sm[OFF_SUM + wid] = s;
    }

    // ---- phase 2: aggregation ----
    float4 pacc0 = {0,0,0,0}, pacc1 = {0,0,0,0};
    float vacc0 = 0.f, vacc1 = 0.f;
    int it0 = -1, it1 = -1, h0i = 0, h1i = 0, st0 = 0, st1 = 0;
    const float* vb0 = nullptr; const float* vb1 = nullptr;
    if (wid >= 6) {
        int t2 = tid - 192;               // 0..319
        it0 = t2;
        it1 = (t2 < 16) ? t2 + 320 : -1;
        st0 = it0 < 192 ? 192 : 144;
        vb0 = it0 < 192 ? (g_vs + it0) : (g_vp + (it0 - 192));
        h0i = it0 < 192 ? (it0 >> 4) : (it0 - 192) / 12;
        if (it1 >= 0) { st1 = 144; vb1 = g_vp + (it1 - 192); h1i = (it1 - 192) / 12; }
    }

    for (int ic = 0; ic < 24; ic++) {
        cp_wait_n(23 - ic);
        __syncthreads();                  // data ic ready; softmax (ic=0) / compute(ic-1) done
        if (ic + 3 < 24) stage(ic + 3);
        int jc = ic * 32;
        if (wid < 6) {                    // r_pair: 2 heads/warp, lanes = d4
            const float4* pwt = pw4 + (ic & 3) * 1056;
            const float* w0 = att + (2 * wid) * ASTRIDE + jc;
            const float* w1 = w0 + ASTRIDE;
            #pragma unroll
            for (int jj = 0; jj < 32; jj++) {
                float4 p = pwt[jj * 33 + lane];
                float a = w0[jj], c = w1[jj];
                pacc0.x += a*p.x; pacc0.y += a*p.y; pacc0.z += a*p.z; pacc0.w += a*p.w;
                pacc1.x += c*p.x; pacc1.y += c*p.y; pacc1.z += c*p.z; pacc1.w += c*p.w;
            }
        } else {                          // v_s / v_p items, coalesced LDG
            const float* w0 = att + h0i * ASTRIDE + jc;
            const float* v0 = vb0 + (size_t)jc * st0;
            #pragma unroll
            for (int jj = 0; jj < 32; jj++) { vacc0 += w0[jj] * v0[0]; v0 += st0; }
            if (it1 >= 0) {
                const float* w1 = att + h1i * ASTRIDE + jc;
                const float* v1 = vb1 + (size_t)jc * st1;
                #pragma unroll
                for (int jj = 0; jj < 32; jj++) { vacc1 += w1[jj] * v1[0]; v1 += st1; }
            }
        }
    }
    __syncthreads();

    // ---- epilogue ----
    float* res = g_results + (size_t)i * 1920;
    if (wid < 6) {
        int h0 = 2 * wid, h1 = h0 + 1;
        float i0v = 1.f / sm[OFF_SUM + h0], i1v = 1.f / sm[OFF_SUM + h1];
        float4 o0 = { pacc0.x*i0v, pacc0.y*i0v, pacc0.z*i0v, pacc0.w*i0v };
        float4 o1 = { pacc1.x*i1v, pacc1.y*i1v, pacc1.z*i1v, pacc1.w*i1v };
        *(float4*)(res + 384 + h0 * 128 + lane * 4) = o0;
        *(float4*)(res + 384 + h1 * 128 + lane * 4) = o1;
    } else {
        float r0v = vacc0 / sm[OFF_SUM + h0i];
        if (it0 < 192) res[it0] = r0v;                 // r_scalar -> [0,192)
        else           sm[OFF_PT + it0 - 192] = r0v;   // global-frame point
        if (it1 >= 0)  sm[OFF_PT + it1 - 192] = vacc1 / sm[OFF_SUM + h1i];
    }
    __syncthreads();
    if (tid < 48) {                       // subtract T, inverse rotate, norms
        int h = tid >> 2, p = tid & 3;
        const float* R = rotations + (size_t)i * 9;
        const float* T = translations + (size_t)i * 3;
        const float* pb = sm + OFF_PT + h * 12 + p * 3;
        float gx = pb[0] - T[0], gy = pb[1] - T[1], gz = pb[2] - T[2];
        float l0 = gx * R[0] + gy * R[3] + gz * R[6];
        float l1 = gx * R[1] + gy * R[4] + gz * R[7];
        float l2 = gx * R[2] + gy * R[5] + gz * R[8];
        res[192 + h * 12 + p * 3 + 0] = l0;
        res[192 + h * 12 + p * 3 + 1] = l1;
        res[192 + h * 12 + p * 3 + 2] = l2;
        res[336 + h * 4 + p] = sqrtf(l0*l0 + l1*l1 + l2*l2 + 1e-8f);
    }
}

// ---- K4a: out GEMM split-K (768x1920)@(1920x384) -> 4 partials ----
__global__ __launch_bounds__(256) void out_part_kernel(const float* __restrict__ Wout)
{
    __shared__ float As[64][33];
    __shared__ float Bs[32][33];
    const int tid = threadIdx.x;
    const int ty = tid >> 4, tx = tid & 15;
    const int r0 = blockIdx.x * 64, c0 = blockIdx.y * 32;
    const int ks = blockIdx.z * 480;
    float acc[4][2] = {{0.f,0.f},{0.f,0.f},{0.f,0.f},{0.f,0.f}};

    for (int k0 = 0; k0 < 480; k0 += 32) {
        #pragma unroll
        for (int l = 0; l < 2; l++) {
            int fidx = tid + l * 256;
            int row = fidx >> 3, c4 = (fidx & 7) * 4;
            float4 v = *(const float4*)(g_results + (size_t)(r0 + row) * 1920 + ks + k0 + c4);
            As[row][c4+0]=v.x; As[row][c4+1]=v.y; As[row][c4+2]=v.z; As[row][c4+3]=v.w;
        }
        #pragma unroll
        for (int l = 0; l < 4; l++) {
            int fidx = tid + l * 256;
            int kk = fidx >> 5, cc = fidx & 31;
            Bs[kk][cc] = Wout[(size_t)(ks + k0 + kk) * 384 + c0 + cc];
        }
        __syncthreads();
        #pragma unroll
        for (int kk = 0; kk < 32; kk++) {
            float b0 = Bs[kk][tx*2+0], b1 = Bs[kk][tx*2+1];
            #pragma unroll
            for (int m = 0; m < 4; m++) {
                float a = As[ty*4+m][kk];
                acc[m][0] += a * b0;
                acc[m][1] += a * b1;
            }
        }
        __syncthreads();
    }
    float* dst = g_part[blockIdx.z];
    #pragma unroll
    for (int m = 0; m < 4; m++) {
        int row = r0 + ty*4 + m;
        #pragma unroll
        for (int n = 0; n < 2; n++)
            dst[(size_t)row * 384 + c0 + tx*2 + n] = acc[m][n];
    }
}

// ---- K4b: sum partials + bias ----
__global__ __launch_bounds__(256) void add_out_kernel(
    const float* __restrict__ bout, float* __restrict__ out)
{
    int idx = blockIdx.x * 256 + threadIdx.x;
    if (idx >= NSEQ * 384) return;
    out[idx] = g_part[0][idx] + g_part[1][idx] + g_part[2][idx] + g_part[3][idx]
             + bout[idx % 384];
}

extern "C" void kernel_launch(void* const* d_in, const int* in_sizes, int n_in,
                              void* d_out, int out_size) {
    const float* x     = (const float*)d_in[0];
    const float* pairw = (const float*)d_in[1];
    const float* rots  = (const float*)d_in[2];
    const float* trans = (const float*)d_in[3];
    // d_in[4] = mask (all true) — unused
    const float* Wqs   = (const float*)d_in[5];
    const float* Wks   = (const float*)d_in[6];
    const float* Wvs   = (const float*)d_in[7];
    const float* Wqp   = (const float*)d_in[8];
    const float* Wkp   = (const float*)d_in[9];
    const float* Wvp   = (const float*)d_in[10];
    const float* Wpair = (const float*)d_in[11];
    const float* bpair = (const float*)d_in[12];
    const float* pwts  = (const float*)d_in[13];
    const float* Wout  = (const float*)d_in[14];
    const float* bout  = (const float*)d_in[15];
    float* out = (float*)d_out;

    static bool attr_set = false;
    if (!attr_set) {
        cudaFuncSetAttribute(fused_attn_kernel,
                             cudaFuncAttributeMaxDynamicSharedMemorySize, SMEM_BYTES);
        attr_set = true;
    }

    proj_kernel<<<dim3(NSEQ / 64, 6, 6), 256>>>(x, Wqs, Wks, Wvs, Wqp, Wkp, Wvp);
    rot_row_kernel<<<(2 * NSEQ * 48 + 255) / 256, 256>>>(rots, trans);
    rot_kt_kernel<<<(48 * NSEQ + 255) / 256, 256>>>(rots, trans);
    fused_attn_kernel<<<NSEQ, 512, SMEM_BYTES>>>(pairw, Wpair, bpair, pwts, rots, trans);
    out_part_kernel<<<dim3(NSEQ / 64, 384 / 32, 4), 256>>>(Wout);
    add_out_kernel<<<(NSEQ * 384 + 255) / 256, 256>>>(bout, out);
}

// round 9
// speedup vs baseline: 1.5712x; 1.1771x over previous
#include <cuda_runtime.h>
#include <cstdint>
#include <cstddef>

#define NSEQ 768
#define DIMM 384
#define NH 12

#define SCALAR_SCALE 0.14433756729740643f   // (3*16)^-0.5
#define POINT_SCALE  0.13608276348795434f   // (3*4*4.5)^-0.5
#define PAIR_SCALE   0.5773502691896258f    // 3^-0.5

// ---- scratch (device globals; allocations forbidden) ----
__device__ float g_qs  [NSEQ * 192];        // [i][h*16+d]
__device__ float g_ks_t[192 * NSEQ];        // [h*16+d][j]   transposed (coalesced dot)
__device__ float g_vs  [NSEQ * 192];        // [j][h*16+d]   row-major (coalesced agg)
__device__ float g_qp  [NSEQ * 144];        // [i][h*12+p*3+c]
__device__ float g_kp_t[144 * NSEQ];        // [h*12+c][j]   transposed
__device__ float g_vp  [NSEQ * 144];        // [j][h*12+c]   row-major
__device__ float g_results[(size_t)NSEQ * 1920];
__device__ float g_part[4][(size_t)NSEQ * 384];

// ---- generic 64x32 fp32 GEMM tile: C = A[M,K] @ B[K,NC] ; tld!=0 => C[col*tld+row] ----
__device__ __forceinline__ void gemm_tile(
    const float* __restrict__ A, const float* __restrict__ B,
    float* __restrict__ C, int K, int NC, int r0, int c0, int tld)
{
    __shared__ float As[64][33];
    __shared__ float Bs[32][33];
    const int tid = threadIdx.x;
    const int ty = tid >> 4, tx = tid & 15;
    float acc[4][2] = {{0.f,0.f},{0.f,0.f},{0.f,0.f},{0.f,0.f}};

    for (int k0 = 0; k0 < K; k0 += 32) {
        #pragma unroll
        for (int l = 0; l < 2; l++) {
            int fidx = tid + l * 256;
            int row = fidx >> 3, c4 = (fidx & 7) * 4;
            float4 v = *(const float4*)(A + (size_t)(r0 + row) * K + k0 + c4);
            As[row][c4 + 0] = v.x; As[row][c4 + 1] = v.y;
            As[row][c4 + 2] = v.z; As[row][c4 + 3] = v.w;
        }
        #pragma unroll
        for (int l = 0; l < 4; l++) {
            int fidx = tid + l * 256;
            int kk = fidx >> 5, cc = fidx & 31;
            int col = c0 + cc;
            Bs[kk][cc] = (col < NC) ? B[(size_t)(k0 + kk) * NC + col] : 0.f;
        }
        __syncthreads();
        #pragma unroll
        for (int kk = 0; kk < 32; kk++) {
            float b0 = Bs[kk][tx * 2 + 0];
            float b1 = Bs[kk][tx * 2 + 1];
            #pragma unroll
            for (int m = 0; m < 4; m++) {
                float a = As[ty * 4 + m][kk];
                acc[m][0] += a * b0;
                acc[m][1] += a * b1;
            }
        }
        __syncthreads();
    }
    #pragma unroll
    for (int m = 0; m < 4; m++) {
        int row = r0 + ty * 4 + m;
        #pragma unroll
        for (int n = 0; n < 2; n++) {
            int col = c0 + tx * 2 + n;
            if (col < NC) {
                if (tld) C[(size_t)col * tld + row] = acc[m][n];
                else     C[(size_t)row * NC  + col] = acc[m][n];
            }
        }
    }
}

// ---- K1: six projection GEMMs; k transposed, v row-major ----
__global__ __launch_bounds__(256) void proj_kernel(
    const float* __restrict__ x,
    const float* __restrict__ Wqs, const float* __restrict__ Wks, const float* __restrict__ Wvs,
    const float* __restrict__ Wqp, const float* __restrict__ Wkp, const float* __restrict__ Wvp)
{
    const float* W; float* C; int NC; int tld;
    switch (blockIdx.z) {
        case 0: W = Wqs; C = g_qs;   NC = 192; tld = 0;    break;
        case 1: W = Wks; C = g_ks_t; NC = 192; tld = NSEQ; break;
        case 2: W = Wvs; C = g_vs;   NC = 192; tld = 0;    break;
        case 3: W = Wqp; C = g_qp;   NC = 144; tld = 0;    break;
        case 4: W = Wkp; C = g_kp_t; NC = 144; tld = NSEQ; break;
        default: W = Wvp; C = g_vp;  NC = 144; tld = 0;    break;
    }
    int c0 = blockIdx.y * 32;
    if (c0 >= NC) return;
    gemm_tile(x, W, C, DIMM, NC, blockIdx.x * 64, c0, tld);
}

// ---- K1b: rotate qp & vp (row-major, in place) ----
__global__ __launch_bounds__(256) void rot_row_kernel(
    const float* __restrict__ R, const float* __restrict__ T)
{
    int tid = blockIdx.x * 256 + threadIdx.x;
    if (tid >= 2 * NSEQ * 48) return;
    int t = tid / (NSEQ * 48);
    int rem = tid - t * (NSEQ * 48);
    int i = rem / 48, item = rem - i * 48;
    float* base = (t ? g_vp : g_qp) + (size_t)i * 144 + item * 3;
    float l0 = base[0], l1 = base[1], l2 = base[2];
    const float* Ri = R + (size_t)i * 9;
    const float* Ti = T + (size_t)i * 3;
    base[0] = Ri[0]*l0 + Ri[1]*l1 + Ri[2]*l2 + Ti[0];
    base[1] = Ri[3]*l0 + Ri[4]*l1 + Ri[5]*l2 + Ti[1];
    base[2] = Ri[6]*l0 + Ri[7]*l1 + Ri[8]*l2 + Ti[2];
}

// ---- K1c: rotate kp_t (transposed layout, coalesced over j) ----
__global__ __launch_bounds__(256) void rot_kt_kernel(
    const float* __restrict__ R, const float* __restrict__ T)
{
    int tid = blockIdx.x * 256 + threadIdx.x;   // 48*768
    if (tid >= 48 * NSEQ) return;
    int item = tid / NSEQ;
    int i = tid - item * NSEQ;
    float* r0p = g_kp_t + (size_t)(item * 3 + 0) * NSEQ + i;
    float* r1p = g_kp_t + (size_t)(item * 3 + 1) * NSEQ + i;
    float* r2p = g_kp_t + (size_t)(item * 3 + 2) * NSEQ + i;
    float l0 = *r0p, l1 = *r1p, l2 = *r2p;
    const float* Ri = R + (size_t)i * 9;
    const float* Ti = T + (size_t)i * 3;
    *r0p = Ri[0]*l0 + Ri[1]*l1 + Ri[2]*l2 + Ti[0];
    *r1p = Ri[3]*l0 + Ri[4]*l1 + Ri[5]*l2 + Ti[1];
    *r2p = Ri[6]*l0 + Ri[7]*l1 + Ri[8]*l2 + Ti[2];
}

// ================= fused: logits (two-pass) + exact softmax + aggregation ======
// 1 query row per CTA. Pairwise streamed twice via 4-buffer cp.async pipeline.

#define ASTRIDE 769
#define OFF_ATT  16896                       // pw: 4 bufs x 1056 f4 = 16896 floats at 0
#define OFF_W    (OFF_ATT + NH * ASTRIDE)    // 12 x 128
#define OFF_QS   (OFF_W + 1536)
#define OFF_QP   (OFF_QS + 192)
#define OFF_BP   (OFF_QP + 144)
#define OFF_CF   (OFF_BP + 12)
#define OFF_SUM  (OFF_CF + 12)
#define OFF_PT   (OFF_SUM + 12)
#define SMEM_FL  (OFF_PT + 144)
#define SMEM_BYTES (SMEM_FL * 4)

__device__ __forceinline__ void cp_wait_n(int n) {
    if (n <= 0)      asm volatile("cp.async.wait_group 0;\n" ::: "memory");
    else if (n == 1) asm volatile("cp.async.wait_group 1;\n" ::: "memory");
    else             asm volatile("cp.async.wait_group 2;\n" ::: "memory");
}

__global__ __launch_bounds__(512, 2) void fused_attn_kernel(
    const float* __restrict__ pairwise, const float* __restrict__ Wp,
    const float* __restrict__ bp, const float* __restrict__ pwts,
    const float* __restrict__ rotations, const float* __restrict__ translations)
{
    extern __shared__ float sm[];
    float4* pw4 = (float4*)sm;
    float* att = sm + OFF_ATT;
    const int i = blockIdx.x;
    const int tid = threadIdx.x;
    const int wid = tid >> 5, lane = tid & 31;
    const uint32_t sbase = (uint32_t)__cvta_generic_to_shared(sm);

    // ---- prologue ----
    for (int idx = tid; idx < NH * 128; idx += 512)           // W_pair transposed [h][d]
        sm[OFF_W + idx] = Wp[(idx & 127) * NH + (idx >> 7)];
    if (tid < 192) sm[OFF_QS + tid] = g_qs[(size_t)i * 192 + tid];
    if (tid < 144) sm[OFF_QP + tid] = g_qp[(size_t)i * 144 + tid];
    if (tid < NH) {
        sm[OFF_BP + tid] = bp[tid];
        sm[OFF_CF + tid] = 0.5f * POINT_SCALE * log1pf(expf(pwts[tid]));
    }

    auto stage = [&](int ic) {
        int b = ic & 3;
        const float4* src = (const float4*)pairwise + ((size_t)i * NSEQ + ic * 32) * 32;
        #pragma unroll
        for (int l = 0; l < 2; l++) {
            int idx = tid + l * 512;
            int slot = b * 1056 + (idx >> 5) * 33 + (idx & 31);
            uint32_t daddr = sbase + (uint32_t)slot * 16;
            asm volatile("cp.async.cg.shared.global [%0], [%1], 16;\n"
                         :: "r"(daddr), "l"(src + idx) : "memory");
        }
        asm volatile("cp.async.commit_group;\n" ::: "memory");
    };

    stage(0); stage(1); stage(2); stage(3);

    // ---- B2 prepass: dot + point dist + pair bias const, coalesced (all 16 warps) ----
    __syncthreads();   // qs/qp/cf ready
    for (int wc = wid; wc < 288; wc += 16) {
        int h = wc / 24, jcc = (wc - h * 24) * 32;
        int j = jcc + lane;
        float dot = 0.f;
        #pragma unroll
        for (int d = 0; d < 16; d++)
            dot += g_ks_t[(size_t)(h * 16 + d) * NSEQ + j] * sm[OFF_QS + h * 16 + d];
        float pd = 0.f;
        #pragma unroll
        for (int c = 0; c < 12; c++) {
            float dd = sm[OFF_QP + h * 12 + c] - g_kp_t[(size_t)(h * 12 + c) * NSEQ + j];
            pd += dd * dd;
        }
        att[h * ASTRIDE + j] = SCALAR_SCALE * dot - sm[OFF_CF + h] * pd
                             + PAIR_SCALE * sm[OFF_BP + h];
    }

    // ---- phase 1: pair bias; warp = (chunk-slot s, head-triple t); no shuffles ----
    // 6 groups of 4 chunks; warp w: s = w>>2 handles chunk 4g+s, heads 3t..3t+2 (t = w&3)
    {
        const int s = wid >> 2, t = wid & 3;
        const float4* wr0 = ((const float4*)(sm + OFF_W)) + (3 * t + 0) * 32;
        const float4* wr1 = wr0 + 32;
        const float4* wr2 = wr1 + 32;
        for (int g = 0; g < 6; g++) {
            asm volatile("cp.async.wait_group 0;\n" ::: "memory");
            __syncthreads();              // all 4 tiles ready; prev compute done
            {
                const float4* prow = pw4 + s * 1056 + lane * 33;
                float a0 = 0.f, a1 = 0.f, a2 = 0.f;
                #pragma unroll
                for (int d = 0; d < 32; d++) {
                    float4 p = prow[d];
                    float4 w0 = wr0[d];   // broadcast
                    float4 w1 = wr1[d];
                    float4 w2 = wr2[d];
                    a0 += p.x*w0.x; a0 += p.y*w0.y; a0 += p.z*w0.z; a0 += p.w*w0.w;
                    a1 += p.x*w1.x; a1 += p.y*w1.y; a1 += p.z*w1.z; a1 += p.w*w1.w;
                    a2 += p.x*w2.x; a2 += p.y*w2.y; a2 += p.z*w2.z; a2 += p.w*w2.w;
                }
                int jj = (4 * g + s) * 32 + lane;
                att[(3 * t + 0) * ASTRIDE + jj] += PAIR_SCALE * a0;
                att[(3 * t + 1) * ASTRIDE + jj] += PAIR_SCALE * a1;
                att[(3 * t + 2) * ASTRIDE + jj] += PAIR_SCALE * a2;
            }
            __syncthreads();              // compute done before restaging buffers
            if (g < 5) {
                stage(4 * (g + 1) + 0); stage(4 * (g + 1) + 1);
                stage(4 * (g + 1) + 2); stage(4 * (g + 1) + 3);
            }
        }
    }

    // ---- restage for phase 2; softmax overlaps cp latency ----
    stage(0); stage(1); stage(2);
    if (wid < 12) {                       // exact softmax per head
        float* row = att + wid * ASTRIDE;
        float m = -1e30f;
        for (int j = lane; j < NSEQ; j += 32) m = fmaxf(m, row[j]);
        #pragma unroll
        for (int o = 16; o; o >>= 1) m = fmaxf(m, __shfl_xor_sync(0xffffffffu, m, o));
        float s = 0.f;
        for (int j = lane; j < NSEQ; j += 32) {
            float e = __expf(row[j] - m);
            row[j] = e;
            s += e;
        }
        #pragma unroll
        for (int o = 16; o; o >>= 1) s += __shfl_xor_sync(0xffffffffu, s, o);
        if (lane == 0) sm[OFF_SUM + wid] = s;
    }

    // ---- phase 2: aggregation; warps 0-3 r_pair (3 heads each), warps 4-15 v-agg ----
    float4 racc0 = {0,0,0,0}, racc1 = {0,0,0,0}, racc2 = {0,0,0,0};
    float vacc = 0.f;
    int it0 = -1, hvi = 0, stv = 0;
    const float* vbase = nullptr;
    if (wid >= 4) {
        int t2 = tid - 128;               // 0..383; 336 items
        if (t2 < 336) {
            it0 = t2;
            stv = it0 < 192 ? 192 : 144;
            vbase = it0 < 192 ? (g_vs + it0) : (g_vp + (it0 - 192));
            hvi = it0 < 192 ? (it0 >> 4) : (it0 - 192) / 12;
        }
    }

    for (int ic = 0; ic < 24; ic++) {
        cp_wait_n(23 - ic);
        __syncthreads();                  // data ic ready; softmax/compute(ic-1) done
        if (ic + 3 < 24) stage(ic + 3);
        int jc = ic * 32;
        if (wid < 4) {                    // r_pair: heads 3*wid..3*wid+2, lanes = d4
            const float4* pwt = pw4 + (ic & 3) * 1056;
            const float* w0 = att + (3 * wid + 0) * ASTRIDE + jc;
            const float* w1 = w0 + ASTRIDE;
            const float* w2 = w1 + ASTRIDE;
            #pragma unroll
            for (int jj = 0; jj < 32; jj++) {
                float4 p = pwt[jj * 33 + lane];
                float a = w0[jj], b = w1[jj], c = w2[jj];
                racc0.x += a*p.x; racc0.y += a*p.y; racc0.z += a*p.z; racc0.w += a*p.w;
                racc1.x += b*p.x; racc1.y += b*p.y; racc1.z += b*p.z; racc1.w += b*p.w;
                racc2.x += c*p.x; racc2.y += c*p.y; racc2.z += c*p.z; racc2.w += c*p.w;
            }
        } else if (it0 >= 0) {            // v_s / v_p items, coalesced LDG
            const float* wr = att + hvi * ASTRIDE + jc;
            const float* v0 = vbase + (size_t)jc * stv;
            #pragma unroll
            for (int jj = 0; jj < 32; jj++) { vacc += wr[jj] * v0[0]; v0 += stv; }
        }
    }
    __syncthreads();

    // ---- epilogue ----
    float* res = g_results + (size_t)i * 1920;
    if (wid < 4) {
        #pragma unroll
        for (int e = 0; e < 3; e++) {
            int h = 3 * wid + e;
            float inv = 1.f / sm[OFF_SUM + h];
            float4 o = (e == 0) ? racc0 : (e == 1) ? racc1 : racc2;
            o.x *= inv; o.y *= inv; o.z *= inv; o.w *= inv;
            *(float4*)(res + 384 + h * 128 + lane * 4) = o;
        }
    } else if (it0 >= 0) {
        float r0v = vacc / sm[OFF_SUM + hvi];
        if (it0 < 192) res[it0] = r0v;                 // r_scalar -> [0,192)
        else           sm[OFF_PT + it0 - 192] = r0v;   // global-frame point
    }
    __syncthreads();
    if (tid < 48) {                       // subtract T, inverse rotate, norms
        int h = tid >> 2, p = tid & 3;
        const float* R = rotations + (size_t)i * 9;
        const float* T = translations + (size_t)i * 3;
        const float* pb = sm + OFF_PT + h * 12 + p * 3;
        float gx = pb[0] - T[0], gy = pb[1] - T[1], gz = pb[2] - T[2];
        float l0 = gx * R[0] + gy * R[3] + gz * R[6];
        float l1 = gx * R[1] + gy * R[4] + gz * R[7];
        float l2 = gx * R[2] + gy * R[5] + gz * R[8];
        res[192 + h * 12 + p * 3 + 0] = l0;
        res[192 + h * 12 + p * 3 + 1] = l1;
        res[192 + h * 12 + p * 3 + 2] = l2;
        res[336 + h * 4 + p] = sqrtf(l0*l0 + l1*l1 + l2*l2 + 1e-8f);
    }
}

// ---- K4a: out GEMM split-K (768x1920)@(1920x384) -> 4 partials ----
__global__ __launch_bounds__(256) void out_part_kernel(const float* __restrict__ Wout)
{
    __shared__ float As[64][33];
    __shared__ float Bs[32][33];
    const int tid = threadIdx.x;
    const int ty = tid >> 4, tx = tid & 15;
    const int r0 = blockIdx.x * 64, c0 = blockIdx.y * 32;
    const int ks = blockIdx.z * 480;
    float acc[4][2] = {{0.f,0.f},{0.f,0.f},{0.f,0.f},{0.f,0.f}};

    for (int k0 = 0; k0 < 480; k0 += 32) {
        #pragma unroll
        for (int l = 0; l < 2; l++) {
            int fidx = tid + l * 256;
            int row = fidx >> 3, c4 = (fidx & 7) * 4;
            float4 v = *(const float4*)(g_results + (size_t)(r0 + row) * 1920 + ks + k0 + c4);
            As[row][c4+0]=v.x; As[row][c4+1]=v.y; As[row][c4+2]=v.z; As[row][c4+3]=v.w;
        }
        #pragma unroll
        for (int l = 0; l < 4; l++) {
            int fidx = tid + l * 256;
            int kk = fidx >> 5, cc = fidx & 31;
            Bs[kk][cc] = Wout[(size_t)(ks + k0 + kk) * 384 + c0 + cc];
        }
        __syncthreads();
        #pragma unroll
        for (int kk = 0; kk < 32; kk++) {
            float b0 = Bs[kk][tx*2+0], b1 = Bs[kk][tx*2+1];
            #pragma unroll
            for (int m = 0; m < 4; m++) {
                float a = As[ty*4+m][kk];
                acc[m][0] += a * b0;
                acc[m][1] += a * b1;
            }
        }
        __syncthreads();
    }
    float* dst = g_part[blockIdx.z];
    #pragma unroll
    for (int m = 0; m < 4; m++) {
        int row = r0 + ty*4 + m;
        #pragma unroll
        for (int n = 0; n < 2; n++)
            dst[(size_t)row * 384 + c0 + tx*2 + n] = acc[m][n];
    }
}

// ---- K4b: sum partials + bias ----
__global__ __launch_bounds__(256) void add_out_kernel(
    const float* __restrict__ bout, float* __restrict__ out)
{
    int idx = blockIdx.x * 256 + threadIdx.x;
    if (idx >= NSEQ * 384) return;
    out[idx] = g_part[0][idx] + g_part[1][idx] + g_part[2][idx] + g_part[3][idx]
             + bout[idx % 384];
}

extern "C" void kernel_launch(void* const* d_in, const int* in_sizes, int n_in,
                              void* d_out, int out_size) {
    const float* x     = (const float*)d_in[0];
    const float* pairw = (const float*)d_in[1];
    const float* rots  = (const float*)d_in[2];
    const float* trans = (const float*)d_in[3];
    // d_in[4] = mask (all true) — unused
    const float* Wqs   = (const float*)d_in[5];
    const float* Wks   = (const float*)d_in[6];
    const float* Wvs   = (const float*)d_in[7];
    const float* Wqp   = (const float*)d_in[8];
    const float* Wkp   = (const float*)d_in[9];
    const float* Wvp   = (const float*)d_in[10];
    const float* Wpair = (const float*)d_in[11];
    const float* bpair = (const float*)d_in[12];
    const float* pwts  = (const float*)d_in[13];
    const float* Wout  = (const float*)d_in[14];
    const float* bout  = (const float*)d_in[15];
    float* out = (float*)d_out;

    static bool attr_set = false;
    if (!attr_set) {
        cudaFuncSetAttribute(fused_attn_kernel,
                             cudaFuncAttributeMaxDynamicSharedMemorySize, SMEM_BYTES);
        attr_set = true;
    }

    proj_kernel<<<dim3(NSEQ / 64, 6, 6), 256>>>(x, Wqs, Wks, Wvs, Wqp, Wkp, Wvp);
    rot_row_kernel<<<(2 * NSEQ * 48 + 255) / 256, 256>>>(rots, trans);
    rot_kt_kernel<<<(48 * NSEQ + 255) / 256, 256>>>(rots, trans);
    fused_attn_kernel<<<NSEQ, 512, SMEM_BYTES>>>(pairw, Wpair, bpair, pwts, rots, trans);
    out_part_kernel<<<dim3(NSEQ / 64, 384 / 32, 4), 256>>>(Wout);
    add_out_kernel<<<(NSEQ * 384 + 255) / 256, 256>>>(bout, out);
}

// round 10
// speedup vs baseline: 1.7434x; 1.1096x over previous
#include <cuda_runtime.h>
#include <cstdint>
#include <cstddef>

#define NSEQ 768
#define DIMM 384
#define NH 12

#define SCALAR_SCALE 0.14433756729740643f   // (3*16)^-0.5
#define POINT_SCALE  0.13608276348795434f   // (3*4*4.5)^-0.5
#define PAIR_SCALE   0.5773502691896258f    // 3^-0.5

// ---- scratch (device globals; allocations forbidden) ----
__device__ float g_qs  [NSEQ * 192];        // [i][h*16+d]
__device__ float g_ks_t[192 * NSEQ];        // [h*16+d][j]   transposed (coalesced dot)
__device__ float g_vs  [NSEQ * 192];        // [j][h*16+d]   row-major (coalesced agg)
__device__ float g_qp  [NSEQ * 144];        // [i][h*12+p*3+c]
__device__ float g_kp_t[144 * NSEQ];        // [h*12+c][j]   transposed
__device__ float g_vp  [NSEQ * 144];        // [j][h*12+c]   row-major
__device__ float g_results[(size_t)NSEQ * 1920];
__device__ float g_part[4][(size_t)NSEQ * 384];

// ---- generic 64x32 fp32 GEMM tile: C = A[M,K] @ B[K,NC] ; tld!=0 => C[col*tld+row] ----
__device__ __forceinline__ void gemm_tile(
    const float* __restrict__ A, const float* __restrict__ B,
    float* __restrict__ C, int K, int NC, int r0, int c0, int tld)
{
    __shared__ float As[64][33];
    __shared__ float Bs[32][33];
    const int tid = threadIdx.x;
    const int ty = tid >> 4, tx = tid & 15;
    float acc[4][2] = {{0.f,0.f},{0.f,0.f},{0.f,0.f},{0.f,0.f}};

    for (int k0 = 0; k0 < K; k0 += 32) {
        #pragma unroll
        for (int l = 0; l < 2; l++) {
            int fidx = tid + l * 256;
            int row = fidx >> 3, c4 = (fidx & 7) * 4;
            float4 v = *(const float4*)(A + (size_t)(r0 + row) * K + k0 + c4);
            As[row][c4 + 0] = v.x; As[row][c4 + 1] = v.y;
            As[row][c4 + 2] = v.z; As[row][c4 + 3] = v.w;
        }
        #pragma unroll
        for (int l = 0; l < 4; l++) {
            int fidx = tid + l * 256;
            int kk = fidx >> 5, cc = fidx & 31;
            int col = c0 + cc;
            Bs[kk][cc] = (col < NC) ? B[(size_t)(k0 + kk) * NC + col] : 0.f;
        }
        __syncthreads();
        #pragma unroll
        for (int kk = 0; kk < 32; kk++) {
            float b0 = Bs[kk][tx * 2 + 0];
            float b1 = Bs[kk][tx * 2 + 1];
            #pragma unroll
            for (int m = 0; m < 4; m++) {
                float a = As[ty * 4 + m][kk];
                acc[m][0] += a * b0;
                acc[m][1] += a * b1;
            }
        }
        __syncthreads();
    }
    #pragma unroll
    for (int m = 0; m < 4; m++) {
        int row = r0 + ty * 4 + m;
        #pragma unroll
        for (int n = 0; n < 2; n++) {
            int col = c0 + tx * 2 + n;
            if (col < NC) {
                if (tld) C[(size_t)col * tld + row] = acc[m][n];
                else     C[(size_t)row * NC  + col] = acc[m][n];
            }
        }
    }
}

// ---- K1: six projection GEMMs; k transposed, v row-major ----
__global__ __launch_bounds__(256) void proj_kernel(
    const float* __restrict__ x,
    const float* __restrict__ Wqs, const float* __restrict__ Wks, const float* __restrict__ Wvs,
    const float* __restrict__ Wqp, const float* __restrict__ Wkp, const float* __restrict__ Wvp)
{
    const float* W; float* C; int NC; int tld;
    switch (blockIdx.z) {
        case 0: W = Wqs; C = g_qs;   NC = 192; tld = 0;    break;
        case 1: W = Wks; C = g_ks_t; NC = 192; tld = NSEQ; break;
        case 2: W = Wvs; C = g_vs;   NC = 192; tld = 0;    break;
        case 3: W = Wqp; C = g_qp;   NC = 144; tld = 0;    break;
        case 4: W = Wkp; C = g_kp_t; NC = 144; tld = NSEQ; break;
        default: W = Wvp; C = g_vp;  NC = 144; tld = 0;    break;
    }
    int c0 = blockIdx.y * 32;
    if (c0 >= NC) return;
    gemm_tile(x, W, C, DIMM, NC, blockIdx.x * 64, c0, tld);
}

// ---- K1b: rotate qp & vp (row-major, in place) ----
__global__ __launch_bounds__(256) void rot_row_kernel(
    const float* __restrict__ R, const float* __restrict__ T)
{
    int tid = blockIdx.x * 256 + threadIdx.x;
    if (tid >= 2 * NSEQ * 48) return;
    int t = tid / (NSEQ * 48);
    int rem = tid - t * (NSEQ * 48);
    int i = rem / 48, item = rem - i * 48;
    float* base = (t ? g_vp : g_qp) + (size_t)i * 144 + item * 3;
    float l0 = base[0], l1 = base[1], l2 = base[2];
    const float* Ri = R + (size_t)i * 9;
    const float* Ti = T + (size_t)i * 3;
    base[0] = Ri[0]*l0 + Ri[1]*l1 + Ri[2]*l2 + Ti[0];
    base[1] = Ri[3]*l0 + Ri[4]*l1 + Ri[5]*l2 + Ti[1];
    base[2] = Ri[6]*l0 + Ri[7]*l1 + Ri[8]*l2 + Ti[2];
}

// ---- K1c: rotate kp_t (transposed layout, coalesced over j) ----
__global__ __launch_bounds__(256) void rot_kt_kernel(
    const float* __restrict__ R, const float* __restrict__ T)
{
    int tid = blockIdx.x * 256 + threadIdx.x;   // 48*768
    if (tid >= 48 * NSEQ) return;
    int item = tid / NSEQ;
    int i = tid - item * NSEQ;
    float* r0p = g_kp_t + (size_t)(item * 3 + 0) * NSEQ + i;
    float* r1p = g_kp_t + (size_t)(item * 3 + 1) * NSEQ + i;
    float* r2p = g_kp_t + (size_t)(item * 3 + 2) * NSEQ + i;
    float l0 = *r0p, l1 = *r1p, l2 = *r2p;
    const float* Ri = R + (size_t)i * 9;
    const float* Ti = T + (size_t)i * 3;
    *r0p = Ri[0]*l0 + Ri[1]*l1 + Ri[2]*l2 + Ti[0];
    *r1p = Ri[3]*l0 + Ri[4]*l1 + Ri[5]*l2 + Ti[1];
    *r2p = Ri[6]*l0 + Ri[7]*l1 + Ri[8]*l2 + Ti[2];
}

// ================= fused: logits (two-pass) + exact softmax + aggregation ======
// 1 query row per CTA. Pairwise streamed twice via 4-buffer cp.async pipeline.

#define ASTRIDE 769
#define OFF_ATT  16896                       // pw: 4 bufs x 1056 f4 = 16896 floats at 0
#define OFF_W    (OFF_ATT + NH * ASTRIDE)    // 12 x 128
#define OFF_QS   (OFF_W + 1536)
#define OFF_QP   (OFF_QS + 192)
#define OFF_BP   (OFF_QP + 144)
#define OFF_CF   (OFF_BP + 12)
#define OFF_SUM  (OFF_CF + 12)
#define OFF_PT   (OFF_SUM + 12)
#define SMEM_FL  (OFF_PT + 144)
#define SMEM_BYTES (SMEM_FL * 4)

__device__ __forceinline__ void cp_wait_n(int n) {
    if (n <= 0)      asm volatile("cp.async.wait_group 0;\n" ::: "memory");
    else if (n == 1) asm volatile("cp.async.wait_group 1;\n" ::: "memory");
    else             asm volatile("cp.async.wait_group 2;\n" ::: "memory");
}

__global__ __launch_bounds__(512, 2) void fused_attn_kernel(
    const float* __restrict__ pairwise, const float* __restrict__ Wp,
    const float* __restrict__ bp, const float* __restrict__ pwts,
    const float* __restrict__ rotations, const float* __restrict__ translations)
{
    extern __shared__ float sm[];
    float4* pw4 = (float4*)sm;
    float* att = sm + OFF_ATT;
    const int i = blockIdx.x;
    const int tid = threadIdx.x;
    const int wid = tid >> 5, lane = tid & 31;
    const uint32_t sbase = (uint32_t)__cvta_generic_to_shared(sm);

    // ---- prologue ----
    for (int idx = tid; idx < NH * 128; idx += 512)           // W_pair transposed [h][d]
        sm[OFF_W + idx] = Wp[(idx & 127) * NH + (idx >> 7)];
    if (tid < 192) sm[OFF_QS + tid] = g_qs[(size_t)i * 192 + tid];
    if (tid < 144) sm[OFF_QP + tid] = g_qp[(size_t)i * 144 + tid];
    if (tid < NH) {
        sm[OFF_BP + tid] = bp[tid];
        sm[OFF_CF + tid] = 0.5f * POINT_SCALE * log1pf(expf(pwts[tid]));
    }

    // staging by all 512 threads (phase 1)
    auto stage = [&](int ic) {
        int b = ic & 3;
        const float4* src = (const float4*)pairwise + ((size_t)i * NSEQ + ic * 32) * 32;
        #pragma unroll
        for (int l = 0; l < 2; l++) {
            int idx = tid + l * 512;
            int slot = b * 1056 + (idx >> 5) * 33 + (idx & 31);
            uint32_t daddr = sbase + (uint32_t)slot * 16;
            asm volatile("cp.async.cg.shared.global [%0], [%1], 16;\n"
                         :: "r"(daddr), "l"(src + idx) : "memory");
        }
        asm volatile("cp.async.commit_group;\n" ::: "memory");
    };
    // staging by warps 0-3 only (phase 2)
    auto stage128 = [&](int ic) {
        int b = ic & 3;
        const float4* src = (const float4*)pairwise + ((size_t)i * NSEQ + ic * 32) * 32;
        #pragma unroll
        for (int l = 0; l < 8; l++) {
            int idx = tid + l * 128;
            int slot = b * 1056 + (idx >> 5) * 33 + (idx & 31);
            uint32_t daddr = sbase + (uint32_t)slot * 16;
            asm volatile("cp.async.cg.shared.global [%0], [%1], 16;\n"
                         :: "r"(daddr), "l"(src + idx) : "memory");
        }
        asm volatile("cp.async.commit_group;\n" ::: "memory");
    };

    // prepass base value for (h, chunk c): att = scalar dot - point dist + bias const
    auto prep_unit = [&](int h, int c) {
        int j = c * 32 + lane;
        float dot = 0.f;
        #pragma unroll
        for (int d = 0; d < 16; d++)
            dot += g_ks_t[(size_t)(h * 16 + d) * NSEQ + j] * sm[OFF_QS + h * 16 + d];
        float pd = 0.f;
        #pragma unroll
        for (int c2 = 0; c2 < 12; c2++) {
            float dd = sm[OFF_QP + h * 12 + c2] - g_kp_t[(size_t)(h * 12 + c2) * NSEQ + j];
            pd += dd * dd;
        }
        att[h * ASTRIDE + j] = SCALAR_SCALE * dot - sm[OFF_CF + h] * pd
                             + PAIR_SCALE * sm[OFF_BP + h];
    };

    stage(0); stage(1); stage(2); stage(3);
    __syncthreads();                       // qs/qp/cf/bp ready

    // warps 8-15 compute prepass for group 0 (chunks 0-3, all heads) pre-loop
    if (wid >= 8) {
        #pragma unroll
        for (int k = 0; k < 6; k++) {
            int u = (wid - 8) + 8 * k;     // 0..47
            prep_unit(u >> 2, u & 3);
        }
    }

    // ---- phase 1: bias (warps 0-7, 6 heads/warp) + prepass g+1 (warps 8-15) ----
    {
        const int s = wid >> 1, t = wid & 1;       // for wid<8: chunk-slot, head-pair
        for (int g = 0; g < 6; g++) {
            asm volatile("cp.async.wait_group 0;\n" ::: "memory");
            __syncthreads();               // tiles(g) + prepass(g) ready; prev compute done
            if (wid < 8) {
                const float4* prow = pw4 + s * 1056 + lane * 33;
                const float4* wbase = ((const float4*)(sm + OFF_W)) + (6 * t) * 32;
                float a0 = 0.f, a1 = 0.f, a2 = 0.f, a3 = 0.f, a4 = 0.f, a5 = 0.f;
                #pragma unroll
                for (int d = 0; d < 32; d++) {
                    float4 p = prow[d];
                    float4 w0 = wbase[d];          // broadcast loads
                    float4 w1 = wbase[32 + d];
                    float4 w2 = wbase[64 + d];
                    float4 w3 = wbase[96 + d];
                    float4 w4 = wbase[128 + d];
                    float4 w5 = wbase[160 + d];
                    a0 += p.x*w0.x; a0 += p.y*w0.y; a0 += p.z*w0.z; a0 += p.w*w0.w;
                    a1 += p.x*w1.x; a1 += p.y*w1.y; a1 += p.z*w1.z; a1 += p.w*w1.w;
                    a2 += p.x*w2.x; a2 += p.y*w2.y; a2 += p.z*w2.z; a2 += p.w*w2.w;
                    a3 += p.x*w3.x; a3 += p.y*w3.y; a3 += p.z*w3.z; a3 += p.w*w3.w;
                    a4 += p.x*w4.x; a4 += p.y*w4.y; a4 += p.z*w4.z; a4 += p.w*w4.w;
                    a5 += p.x*w5.x; a5 += p.y*w5.y; a5 += p.z*w5.z; a5 += p.w*w5.w;
                }
                int jj = (4 * g + s) * 32 + lane;
                att[(6*t + 0) * ASTRIDE + jj] += PAIR_SCALE * a0;
                att[(6*t + 1) * ASTRIDE + jj] += PAIR_SCALE * a1;
                att[(6*t + 2) * ASTRIDE + jj] += PAIR_SCALE * a2;
                att[(6*t + 3) * ASTRIDE + jj] += PAIR_SCALE * a3;
                att[(6*t + 4) * ASTRIDE + jj] += PAIR_SCALE * a4;
                att[(6*t + 5) * ASTRIDE + jj] += PAIR_SCALE * a5;
            } else if (g < 5) {            // prepass for group g+1 (chunks 4g+4..4g+7)
                #pragma unroll
                for (int k = 0; k < 6; k++) {
                    int u = (wid - 8) + 8 * k;
                    prep_unit(u >> 2, 4 * (g + 1) + (u & 3));
                }
            }
            __syncthreads();               // compute done before re-staging buffers
            if (g < 5) {
                stage(4 * (g + 1) + 0); stage(4 * (g + 1) + 1);
                stage(4 * (g + 1) + 2); stage(4 * (g + 1) + 3);
            }
        }
    }

    // ---- restage (warps 0-3 only) for phase 2; softmax overlaps cp latency ----
    if (wid < 4) { stage128(0); stage128(1); stage128(2); }
    if (wid < 12) {                        // exact softmax per head
        float* row = att + wid * ASTRIDE;
        float m = -1e30f;
        for (int j = lane; j < NSEQ; j += 32) m = fmaxf(m, row[j]);
        #pragma unroll
        for (int o = 16; o; o >>= 1) m = fmaxf(m, __shfl_xor_sync(0xffffffffu, m, o));
        float s = 0.f;
        for (int j = lane; j < NSEQ; j += 32) {
            float e = __expf(row[j] - m);
            row[j] = e;
            s += e;
        }
        #pragma unroll
        for (int o = 16; o; o >>= 1) s += __shfl_xor_sync(0xffffffffu, s, o);
        if (lane == 0) sm[OFF_SUM + wid] = s;
    }
    __syncthreads();                       // att exp-weights final for all heads

    // ---- phase 2: r_pair (warps 0-3, private barrier) || v-agg (warps 4-15) ----
    float4 racc0 = {0,0,0,0}, racc1 = {0,0,0,0}, racc2 = {0,0,0,0};
    float vacc = 0.f;
    int it0 = -1, hvi = 0, stv = 0;
    const float* vbase = nullptr;

    if (wid < 4) {
        for (int ic = 0; ic < 24; ic++) {
            cp_wait_n(23 - ic);
            asm volatile("bar.sync 1, 128;\n" ::: "memory");   // warps 0-3 only
            if (ic + 3 < 24) stage128(ic + 3);
            int jc = ic * 32;
            const float4* pwt = pw4 + (ic & 3) * 1056;
            const float* w0 = att + (3 * wid + 0) * ASTRIDE + jc;
            const float* w1 = w0 + ASTRIDE;
            const float* w2 = w1 + ASTRIDE;
            #pragma unroll
            for (int jj = 0; jj < 32; jj++) {
                float4 p = pwt[jj * 33 + lane];
                float a = w0[jj], b = w1[jj], c = w2[jj];
                racc0.x += a*p.x; racc0.y += a*p.y; racc0.z += a*p.z; racc0.w += a*p.w;
                racc1.x += b*p.x; racc1.y += b*p.y; racc1.z += b*p.z; racc1.w += b*p.w;
                racc2.x += c*p.x; racc2.y += c*p.y; racc2.z += c*p.z; racc2.w += c*p.w;
            }
        }
    } else {
        int t2 = tid - 128;                // 0..383; 336 items
        if (t2 < 336) {
            it0 = t2;
            stv = it0 < 192 ? 192 : 144;
            vbase = it0 < 192 ? (g_vs + it0) : (g_vp + (it0 - 192));
            hvi = it0 < 192 ? (it0 >> 4) : (it0 - 192) / 12;
            const float* wr = att + hvi * ASTRIDE;
            const float* v0 = vbase;
            #pragma unroll 8
            for (int j = 0; j < NSEQ; j++) { vacc += wr[j] * v0[0]; v0 += stv; }
        }
    }
    __syncthreads();

    // ---- epilogue ----
    float* res = g_results + (size_t)i * 1920;
    if (wid < 4) {
        #pragma unroll
        for (int e = 0; e < 3; e++) {
            int h = 3 * wid + e;
            float inv = 1.f / sm[OFF_SUM + h];
            float4 o = (e == 0) ? racc0 : (e == 1) ? racc1 : racc2;
            o.x *= inv; o.y *= inv; o.z *= inv; o.w *= inv;
            *(float4*)(res + 384 + h * 128 + lane * 4) = o;
        }
    } else if (it0 >= 0) {
        float r0v = vacc / sm[OFF_SUM + hvi];
        if (it0 < 192) res[it0] = r0v;                 // r_scalar -> [0,192)
        else           sm[OFF_PT + it0 - 192] = r0v;   // global-frame point
    }
    __syncthreads();
    if (tid < 48) {                        // subtract T, inverse rotate, norms
        int h = tid >> 2, p = tid & 3;
        const float* R = rotations + (size_t)i * 9;
        const float* T = translations + (size_t)i * 3;
        const float* pb = sm + OFF_PT + h * 12 + p * 3;
        float gx = pb[0] - T[0], gy = pb[1] - T[1], gz = pb[2] - T[2];
        float l0 = gx * R[0] + gy * R[3] + gz * R[6];
        float l1 = gx * R[1] + gy * R[4] + gz * R[7];
        float l2 = gx * R[2] + gy * R[5] + gz * R[8];
        res[192 + h * 12 + p * 3 + 0] = l0;
        res[192 + h * 12 + p * 3 + 1] = l1;
        res[192 + h * 12 + p * 3 + 2] = l2;
        res[336 + h * 4 + p] = sqrtf(l0*l0 + l1*l1 + l2*l2 + 1e-8f);
    }
}

// ---- K4a: out GEMM split-K (768x1920)@(1920x384) -> 4 partials ----
__global__ __launch_bounds__(256) void out_part_kernel(const float* __restrict__ Wout)
{
    __shared__ float As[64][33];
    __shared__ float Bs[32][33];
    const int tid = threadIdx.x;
    const int ty = tid >> 4, tx = tid & 15;
    const int r0 = blockIdx.x * 64, c0 = blockIdx.y * 32;
    const int ks = blockIdx.z * 480;
    float acc[4][2] = {{0.f,0.f},{0.f,0.f},{0.f,0.f},{0.f,0.f}};

    for (int k0 = 0; k0 < 480; k0 += 32) {
        #pragma unroll
        for (int l = 0; l < 2; l++) {
            int fidx = tid + l * 256;
            int row = fidx >> 3, c4 = (fidx & 7) * 4;
            float4 v = *(const float4*)(g_results + (size_t)(r0 + row) * 1920 + ks + k0 + c4);
            As[row][c4+0]=v.x; As[row][c4+1]=v.y; As[row][c4+2]=v.z; As[row][c4+3]=v.w;
        }
        #pragma unroll
        for (int l = 0; l < 4; l++) {
            int fidx = tid + l * 256;
            int kk = fidx >> 5, cc = fidx & 31;
            Bs[kk][cc] = Wout[(size_t)(ks + k0 + kk) * 384 + c0 + cc];
        }
        __syncthreads();
        #pragma unroll
        for (int kk = 0; kk < 32; kk++) {
            float b0 = Bs[kk][tx*2+0], b1 = Bs[kk][tx*2+1];
            #pragma unroll
            for (int m = 0; m < 4; m++) {
                float a = As[ty*4+m][kk];
                acc[m][0] += a * b0;
                acc[m][1] += a * b1;
            }
        }
        __syncthreads();
    }
    float* dst = g_part[blockIdx.z];
    #pragma unroll
    for (int m = 0; m < 4; m++) {
        int row = r0 + ty*4 + m;
        #pragma unroll
        for (int n = 0; n < 2; n++)
            dst[(size_t)row * 384 + c0 + tx*2 + n] = acc[m][n];
    }
}

// ---- K4b: sum partials + bias ----
__global__ __launch_bounds__(256) void add_out_kernel(
    const float* __restrict__ bout, float* __restrict__ out)
{
    int idx = blockIdx.x * 256 + threadIdx.x;
    if (idx >= NSEQ * 384) return;
    out[idx] = g_part[0][idx] + g_part[1][idx] + g_part[2][idx] + g_part[3][idx]
             + bout[idx % 384];
}

extern "C" void kernel_launch(void* const* d_in, const int* in_sizes, int n_in,
                              void* d_out, int out_size) {
    const float* x     = (const float*)d_in[0];
    const float* pairw = (const float*)d_in[1];
    const float* rots  = (const float*)d_in[2];
    const float* trans = (const float*)d_in[3];
    // d_in[4] = mask (all true) — unused
    const float* Wqs   = (const float*)d_in[5];
    const float* Wks   = (const float*)d_in[6];
    const float* Wvs   = (const float*)d_in[7];
    const float* Wqp   = (const float*)d_in[8];
    const float* Wkp   = (const float*)d_in[9];
    const float* Wvp   = (const float*)d_in[10];
    const float* Wpair = (const float*)d_in[11];
    const float* bpair = (const float*)d_in[12];
    const float* pwts  = (const float*)d_in[13];
    const float* Wout  = (const float*)d_in[14];
    const float* bout  = (const float*)d_in[15];
    float* out = (float*)d_out;

    static bool attr_set = false;
    if (!attr_set) {
        cudaFuncSetAttribute(fused_attn_kernel,
                             cudaFuncAttributeMaxDynamicSharedMemorySize, SMEM_BYTES);
        attr_set = true;
    }

    proj_kernel<<<dim3(NSEQ / 64, 6, 6), 256>>>(x, Wqs, Wks, Wvs, Wqp, Wkp, Wvp);
    rot_row_kernel<<<(2 * NSEQ * 48 + 255) / 256, 256>>>(rots, trans);
    rot_kt_kernel<<<(48 * NSEQ + 255) / 256, 256>>>(rots, trans);
    fused_attn_kernel<<<NSEQ, 512, SMEM_BYTES>>>(pairw, Wpair, bpair, pwts, rots, trans);
    out_part_kernel<<<dim3(NSEQ / 64, 384 / 32, 4), 256>>>(Wout);
    add_out_kernel<<<(NSEQ * 384 + 255) / 256, 256>>>(bout, out);
}